// round 11
// baseline (speedup 1.0000x reference)
#include <cuda_runtime.h>

// PTDNet-GCN fused pipeline, round 10:
//  - GEMM: PER-WARP decoupled cp.async pipeline. Each warp owns a 32-row strip
//    with its own 2-stage smem ring (cp.async groups are per-thread, so no
//    __syncthreads anywhere in the mainloop). m16n8k8 tf32, 3xTF32 compensation.
//  - Everything else as the best-known configuration.

#define N_NODES 100000
#define N_EDGES 1600000
#define IN_DIM  512
#define H0      32
#define H1      8
#define ZETA    1.01f
#define NB_SCAN 98            // ceil(100000/1024)

// ---------------- scratch (static device memory) ----------------------------
__device__ float  g_xw[N_NODES * H0];     // dinv0[row] * (x @ W0)
__device__ float  g_hw[N_NODES * H1];     // h @ W1
__device__ float  g_hws[N_NODES * H1];    // dinv1[row] * hw
__device__ int    g_cnt[N_NODES];
__device__ int    g_off[N_NODES];         // bucket start (non-monotone partition)
__device__ int    g_cursor[N_NODES];
__device__ int    g_total;
__device__ int    g_src[N_EDGES];
__device__ float  g_mw[N_EDGES];
__device__ float  g_dinv0[N_NODES];
__device__ float  g_dinv1[N_NODES];
__device__ float  g_u[N_NODES];
__device__ float  g_v[N_NODES];
__device__ float  g_att_a[H0];
__device__ float  g_att_b[H0];
__device__ float  g_cst;
// W0 fragments: [64 k-steps][4 n-tiles][32 lanes] -> (b0_hi, b1_hi, b0_lo, b1_lo)
__device__ float4 g_wf[64 * 4 * 32];

// ---------------- helpers ---------------------------------------------------
__device__ __forceinline__ float wred(float x) {
    x += __shfl_xor_sync(0xffffffffu, x, 16);
    x += __shfl_xor_sync(0xffffffffu, x, 8);
    x += __shfl_xor_sync(0xffffffffu, x, 4);
    x += __shfl_xor_sync(0xffffffffu, x, 2);
    x += __shfl_xor_sync(0xffffffffu, x, 1);
    return x;
}

__device__ __forceinline__ unsigned f2tf(float x) {
    unsigned u;
    asm("cvt.rna.tf32.f32 %0, %1;" : "=r"(u) : "f"(x));
    return u;
}

__device__ __forceinline__ void mma_tf32(float* d, const unsigned* a,
                                         unsigned b0, unsigned b1) {
    asm("mma.sync.aligned.m16n8k8.row.col.f32.tf32.tf32.f32 "
        "{%0,%1,%2,%3}, {%4,%5,%6,%7}, {%8,%9}, {%0,%1,%2,%3};"
        : "+f"(d[0]), "+f"(d[1]), "+f"(d[2]), "+f"(d[3])
        : "r"(a[0]), "r"(a[1]), "r"(a[2]), "r"(a[3]), "r"(b0), "r"(b1));
}

// ---------------- 1) zero counters + attn prep + W fragment swizzle ----------
__global__ __launch_bounds__(1024) void zero_prep(
        const float* __restrict__ W0,
        const float* __restrict__ Wnb, const float* __restrict__ bnb,
        const float* __restrict__ Wself, const float* __restrict__ bself,
        const float* __restrict__ Watt, const float* __restrict__ batt) {
    int i = blockIdx.x * 1024 + threadIdx.x;
    if (i < N_NODES) g_cnt[i] = 0;
    if (blockIdx.x == 0) {
        if (threadIdx.x == 0) g_total = 0;
        if (threadIdx.x < 32) {
            int j = threadIdx.x;
            float a = 0.f, b = 0.f;
#pragma unroll
            for (int q = 0; q < 8; ++q) {
                a += Wnb[j * 8 + q] * Watt[q];
                b += Wself[j * 8 + q] * Watt[8 + q];
            }
            g_att_a[j] = a;
            g_att_b[j] = b;
            if (j == 0) {
                float c = batt[0];
#pragma unroll
                for (int q = 0; q < 8; ++q)
                    c += bnb[q] * Watt[q] + bself[q] * Watt[8 + q];
                g_cst = c;
            }
        }
    } else if (blockIdx.x <= 8) {
        // W fragment swizzle: idx over 64*4*32 = 8192 entries
        int idx = (blockIdx.x - 1) * 1024 + threadIdx.x;
        int s = idx >> 7;            // k-step
        int t = (idx >> 5) & 3;      // n-tile
        int lane = idx & 31;
        int tig = lane & 3, gid = lane >> 2;
        float b0 = W0[(8 * s + tig) * 32 + 8 * t + gid];
        float b1 = W0[(8 * s + tig + 4) * 32 + 8 * t + gid];
        unsigned b0h = f2tf(b0), b1h = f2tf(b1);
        float b0hf = __uint_as_float(b0h), b1hf = __uint_as_float(b1h);
        unsigned b0l = f2tf(b0 - b0hf), b1l = f2tf(b1 - b1hf);
        g_wf[idx] = make_float4(b0hf, b1hf,
                                __uint_as_float(b0l), __uint_as_float(b1l));
    }
}

// ---------------- 2) in-degree count (4 edges / thread, int4) ----------------
__global__ void count_kernel(const int* __restrict__ eidx) {
    int t = blockIdx.x * blockDim.x + threadIdx.x;
    if (t >= N_EDGES / 4) return;
    int4 c = *(const int4*)(eidx + N_EDGES + t * 4);
    atomicAdd(&g_cnt[c.x], 1);
    atomicAdd(&g_cnt[c.y], 1);
    atomicAdd(&g_cnt[c.z], 1);
    atomicAdd(&g_cnt[c.w], 1);
}

// ---------------- 3) fused scan: block-local scan + atomic base --------------
__global__ __launch_bounds__(1024) void scan_fused() {
    __shared__ int sm[1024];
    __shared__ int sbase;
    int tid = threadIdx.x;
    int i = blockIdx.x * 1024 + tid;
    int v = (i < N_NODES) ? g_cnt[i] : 0;
    sm[tid] = v;
    __syncthreads();
    for (int o = 1; o < 1024; o <<= 1) {
        int t = (tid >= o) ? sm[tid - o] : 0;
        __syncthreads();
        sm[tid] += t;
        __syncthreads();
    }
    if (tid == 1023) sbase = atomicAdd(&g_total, sm[1023]);
    __syncthreads();
    if (i < N_NODES) {
        int o = sm[tid] - v + sbase;
        g_off[i] = o;
        g_cursor[i] = o;
        g_dinv0[i] = rsqrtf((float)v + 1.0f);
    }
}

// ---------------- 4) xw = dinv0 * (x @ W0)  (per-warp cp.async pipeline) -----
// 256 threads / 8 warps; warp owns 32 rows with a private 2-stage ring.
// Stage = 32 rows x 16 k-floats, row stride 20 floats (80 B: 16B-aligned +
// conflict-free bank pattern). cp.async groups are per-thread -> warps fully
// decoupled; only __syncwarp in the mainloop.
#define KC    16                  // k-floats per chunk (2 k-steps)
#define CPAD  20                  // padded row stride (floats)
#define NCH   (IN_DIM / KC)       // 32 chunks
#define WSTG  (32 * CPAD)         // floats per stage per warp
__global__ __launch_bounds__(256) void gemm_xw(const float* __restrict__ x) {
    __shared__ float xs[8 * 2 * WSTG];     // 40960 B
    int tid = threadIdx.x;
    int lane = tid & 31;
    int warp = tid >> 5;
    int row0 = blockIdx.x * 256 + warp * 32;
    if (row0 >= N_NODES) return;           // whole-strip guard (N % 32 == 0)
    int gid = lane >> 2, tig = lane & 3;
    float* st = xs + warp * 2 * WSTG;
    const float* xrow = x + (size_t)(row0 + lane) * IN_DIM;  // lane = row

    // issue chunk c into stage c&1 (each lane copies its own row's 64 B)
    auto issue = [&](int c) {
        const float* src = xrow + c * KC;
        unsigned dst = (unsigned)__cvta_generic_to_shared(
            st + (c & 1) * WSTG + lane * CPAD);
        asm volatile("cp.async.ca.shared.global [%0], [%1], 16;\n"
                     "cp.async.ca.shared.global [%2], [%3], 16;\n"
                     "cp.async.ca.shared.global [%4], [%5], 16;\n"
                     "cp.async.ca.shared.global [%6], [%7], 16;\n"
                     :: "r"(dst), "l"(src),
                        "r"(dst + 16), "l"(src + 4),
                        "r"(dst + 32), "l"(src + 8),
                        "r"(dst + 48), "l"(src + 12));
        asm volatile("cp.async.commit_group;");
    };

    float acc[2][4][4];
#pragma unroll
    for (int m = 0; m < 2; ++m)
#pragma unroll
        for (int t = 0; t < 4; ++t)
#pragma unroll
            for (int r = 0; r < 4; ++r) acc[m][t][r] = 0.f;

    issue(0);
    issue(1);

    for (int c = 0; c < NCH; ++c) {
        if (c < NCH - 1) asm volatile("cp.async.wait_group 1;");
        else             asm volatile("cp.async.wait_group 0;");
        __syncwarp();
        const float* sb = st + (c & 1) * WSTG;

#pragma unroll
        for (int ks = 0; ks < 2; ++ks) {
            int s = c * 2 + ks;              // global k-step 0..63
            int kk = ks * 8 + tig;
            float a[2][4];
            a[0][0] = sb[(gid     ) * CPAD + kk];
            a[0][1] = sb[(gid + 8 ) * CPAD + kk];
            a[0][2] = sb[(gid     ) * CPAD + kk + 4];
            a[0][3] = sb[(gid + 8 ) * CPAD + kk + 4];
            a[1][0] = sb[(gid + 16) * CPAD + kk];
            a[1][1] = sb[(gid + 24) * CPAD + kk];
            a[1][2] = sb[(gid + 16) * CPAD + kk + 4];
            a[1][3] = sb[(gid + 24) * CPAD + kk + 4];

            unsigned ah[2][4], al[2][4];
#pragma unroll
            for (int m = 0; m < 2; ++m)
#pragma unroll
                for (int j = 0; j < 4; ++j) {
                    unsigned h = f2tf(a[m][j]);
                    ah[m][j] = h;
                    al[m][j] = f2tf(a[m][j] - __uint_as_float(h));
                }

#pragma unroll
            for (int t = 0; t < 4; ++t) {
                float4 w = __ldg(&g_wf[(s * 4 + t) * 32 + lane]);
                unsigned bh0 = __float_as_uint(w.x), bh1 = __float_as_uint(w.y);
                unsigned bl0 = __float_as_uint(w.z), bl1 = __float_as_uint(w.w);
#pragma unroll
                for (int m = 0; m < 2; ++m) {
                    mma_tf32(acc[m][t], ah[m], bh0, bh1);
                    mma_tf32(acc[m][t], al[m], bh0, bh1);
                    mma_tf32(acc[m][t], ah[m], bl0, bl1);
                }
            }
        }
        __syncwarp();                        // all lanes done reading stage
        if (c + 2 < NCH) issue(c + 2);       // overwrite stage (c&1)
    }

    // epilogue: scale rows by rsqrt(indeg+1), store float2 pairs
#pragma unroll
    for (int m = 0; m < 2; ++m) {
        int rA = row0 + m * 16 + gid;
        int rB = rA + 8;
        float dA = rsqrtf((float)g_cnt[rA] + 1.f);
        float dB = rsqrtf((float)g_cnt[rB] + 1.f);
#pragma unroll
        for (int t = 0; t < 4; ++t) {
            int col = t * 8 + tig * 2;
            *(float2*)(g_xw + rA * 32 + col) =
                make_float2(acc[m][t][0] * dA, acc[m][t][1] * dA);
            *(float2*)(g_xw + rB * 32 + col) =
                make_float2(acc[m][t][2] * dB, acc[m][t][3] * dB);
        }
    }
}

// ---------------- 5) CSR fill (2 edges / thread, batched loads) --------------
__global__ void fill_kernel(const int* __restrict__ eidx) {
    int t = blockIdx.x * blockDim.x + threadIdx.x;
    if (t >= N_EDGES / 2) return;
    int2 r = *(const int2*)(eidx + t * 2);
    int2 c = *(const int2*)(eidx + N_EDGES + t * 2);
    int pos0 = atomicAdd(&g_cursor[c.x], 1);
    int pos1 = atomicAdd(&g_cursor[c.y], 1);
    g_src[pos0] = r.x;
    g_src[pos1] = r.y;
}

// ---------------- 6) conv0 + fused (hw, u, v) --------------------------------
__global__ __launch_bounds__(256) void conv0_kernel(const float* __restrict__ b0,
                                                    const float* __restrict__ W1) {
    __shared__ float hsm[8][32];
    int warp = (blockIdx.x * blockDim.x + threadIdx.x) >> 5;
    int lane = threadIdx.x & 31;
    int w = threadIdx.x >> 5;
    if (warp >= N_NODES) return;
    int node = warp;
    int s = g_off[node];
    int e = s + g_cnt[node];
    int g = lane >> 3;
    int f4 = (lane & 7) * 4;

    float4 acc;
    if (g == 0) acc = *(const float4*)(g_xw + node * 32 + f4);  // self (pre-scaled)
    else        acc = make_float4(0.f, 0.f, 0.f, 0.f);

    for (int p0 = s; p0 < e; p0 += 8) {
        int pA = p0 + g;
        int pB = p0 + 4 + g;
        int rA = (pA < e) ? g_src[pA] : -1;
        int rB = (pB < e) ? g_src[pB] : -1;
        if (rA >= 0) {
            float4 xv = *(const float4*)(g_xw + rA * 32 + f4);
            acc.x += xv.x; acc.y += xv.y; acc.z += xv.z; acc.w += xv.w;
        }
        if (rB >= 0) {
            float4 xv = *(const float4*)(g_xw + rB * 32 + f4);
            acc.x += xv.x; acc.y += xv.y; acc.z += xv.z; acc.w += xv.w;
        }
    }
    acc.x += __shfl_xor_sync(0xffffffffu, acc.x, 8);
    acc.y += __shfl_xor_sync(0xffffffffu, acc.y, 8);
    acc.z += __shfl_xor_sync(0xffffffffu, acc.z, 8);
    acc.w += __shfl_xor_sync(0xffffffffu, acc.w, 8);
    acc.x += __shfl_xor_sync(0xffffffffu, acc.x, 16);
    acc.y += __shfl_xor_sync(0xffffffffu, acc.y, 16);
    acc.z += __shfl_xor_sync(0xffffffffu, acc.z, 16);
    acc.w += __shfl_xor_sync(0xffffffffu, acc.w, 16);

    float dc = g_dinv0[node];
    if (g == 0) {
        hsm[w][f4 + 0] = dc * acc.x + __ldg(b0 + f4 + 0);
        hsm[w][f4 + 1] = dc * acc.y + __ldg(b0 + f4 + 1);
        hsm[w][f4 + 2] = dc * acc.z + __ldg(b0 + f4 + 2);
        hsm[w][f4 + 3] = dc * acc.w + __ldg(b0 + f4 + 3);
    }
    __syncwarp();

    float q = 0.f;
    if (lane < 8) {
#pragma unroll
        for (int j = 0; j < 32; ++j) q += hsm[w][j] * __ldg(W1 + j * 8 + lane);
        g_hw[node * 8 + lane] = q;
    } else if (lane == 8) {
#pragma unroll
        for (int j = 0; j < 32; ++j) q += hsm[w][j] * g_att_a[j];
        g_u[node] = q;
    } else if (lane == 9) {
#pragma unroll
        for (int j = 0; j < 32; ++j) q += hsm[w][j] * g_att_b[j];
        g_v[node] = q;
    }
}

// ---------------- 7) attention weights + dinv1 + hws -------------------------
__global__ __launch_bounds__(256) void attn_kernel() {
    int warp = (blockIdx.x * blockDim.x + threadIdx.x) >> 5;
    int lane = threadIdx.x & 31;
    if (warp >= N_NODES) return;
    int node = warp;
    float vc = g_v[node] + g_cst;
    int s = g_off[node];
    int e = s + g_cnt[node];
    float sum = 0.f;
    for (int p0 = s; p0 < e; p0 += 32) {
        int p = p0 + lane;
        float mw = 0.f;
        if (p < e) {
            int r = g_src[p];
            float wgt = fmaxf(g_u[r] + vc, 0.f);
            float m = fminf(ZETA / (1.f + __expf(-wgt)), 1.f);
            mw = m * wgt;
            g_mw[p] = mw;
        }
        sum += mw;
    }
    sum = wred(sum);
    float d1 = rsqrtf(sum + 1.0f);
    if (lane == 0) g_dinv1[node] = d1;
    if (lane < 8) g_hws[node * 8 + lane] = d1 * g_hw[node * 8 + lane];
}

// ---------------- 8) conv1 ---------------------------------------------------
__global__ __launch_bounds__(256) void conv1_kernel(const float* __restrict__ b1,
                                                    float* __restrict__ out) {
    int warp = (blockIdx.x * blockDim.x + threadIdx.x) >> 5;
    int lane = threadIdx.x & 31;
    if (warp >= N_NODES) return;
    int node = warp;
    int s = g_off[node];
    int e = s + g_cnt[node];
    int g = lane >> 3;
    int f = lane & 7;

    float acc = (g == 0) ? g_hws[node * 8 + f] : 0.f;  // self term

    for (int p0 = s; p0 < e; p0 += 8) {
        int pA = p0 + g;
        int pB = p0 + 4 + g;
        int rA = (pA < e) ? g_src[pA] : -1;
        int rB = (pB < e) ? g_src[pB] : -1;
        float cA = (pA < e) ? g_mw[pA] : 0.f;
        float cB = (pB < e) ? g_mw[pB] : 0.f;
        if (rA >= 0) acc += cA * g_hws[rA * 8 + f];
        if (rB >= 0) acc += cB * g_hws[rB * 8 + f];
    }
    acc += __shfl_xor_sync(0xffffffffu, acc, 8);
    acc += __shfl_xor_sync(0xffffffffu, acc, 16);

    if (lane < 8)
        out[node * 8 + lane] = g_dinv1[node] * acc + __ldg(b1 + lane);
}

// ---------------- launch -----------------------------------------------------
extern "C" void kernel_launch(void* const* d_in, const int* in_sizes, int n_in,
                              void* d_out, int out_size) {
    const float* x     = (const float*)d_in[0];
    const int*   eidx  = (const int*)  d_in[1];
    const float* W0    = (const float*)d_in[2];
    const float* b0    = (const float*)d_in[3];
    const float* W1    = (const float*)d_in[4];
    const float* b1    = (const float*)d_in[5];
    const float* Wnb   = (const float*)d_in[6];
    const float* bnb   = (const float*)d_in[7];
    const float* Wself = (const float*)d_in[8];
    const float* bself = (const float*)d_in[9];
    const float* Watt  = (const float*)d_in[10];
    const float* batt  = (const float*)d_in[11];
    float* out = (float*)d_out;

    zero_prep<<<NB_SCAN, 1024>>>(W0, Wnb, bnb, Wself, bself, Watt, batt);     // 0
    count_kernel<<<(N_EDGES / 4 + 255) / 256, 256>>>(eidx);                   // 1
    scan_fused<<<NB_SCAN, 1024>>>();                                          // 2
    gemm_xw<<<(N_NODES + 255) / 256, 256>>>(x);                               // 3 (profiled)
    fill_kernel<<<(N_EDGES / 2 + 255) / 256, 256>>>(eidx);                    // 4
    conv0_kernel<<<(N_NODES * 32 + 255) / 256, 256>>>(b0, W1);                // 5
    attn_kernel<<<(N_NODES * 32 + 255) / 256, 256>>>();                       // 6
    conv1_kernel<<<(N_NODES * 32 + 255) / 256, 256>>>(b1, out);               // 7
}

// round 12
// speedup vs baseline: 1.4712x; 1.4712x over previous
#include <cuda_runtime.h>

// PTDNet-GCN fused pipeline, round 11:
//  - GEMM: block-wide coalesced cp.async staging with a 4-STAGE ring and
//    wait_group 3 (three 8KB chunks in flight per block -> ~120 KB/SM).
//    m16n8k8 tf32, 3xTF32 compensation. Tail uses empty commit_groups so the
//    wait constant stays 3.
//  - Everything else as the best-known configuration.

#define N_NODES 100000
#define N_EDGES 1600000
#define IN_DIM  512
#define H0      32
#define H1      8
#define ZETA    1.01f
#define NB_SCAN 98            // ceil(100000/1024)

// ---------------- scratch (static device memory) ----------------------------
__device__ float  g_xw[N_NODES * H0];     // dinv0[row] * (x @ W0)
__device__ float  g_hw[N_NODES * H1];     // h @ W1
__device__ float  g_hws[N_NODES * H1];    // dinv1[row] * hw
__device__ int    g_cnt[N_NODES];
__device__ int    g_off[N_NODES];         // bucket start (non-monotone partition)
__device__ int    g_cursor[N_NODES];
__device__ int    g_total;
__device__ int    g_src[N_EDGES];
__device__ float  g_mw[N_EDGES];
__device__ float  g_dinv0[N_NODES];
__device__ float  g_dinv1[N_NODES];
__device__ float  g_u[N_NODES];
__device__ float  g_v[N_NODES];
__device__ float  g_att_a[H0];
__device__ float  g_att_b[H0];
__device__ float  g_cst;
// W0 fragments: [64 k-steps][4 n-tiles][32 lanes] -> (b0_hi, b1_hi, b0_lo, b1_lo)
__device__ float4 g_wf[64 * 4 * 32];

// ---------------- helpers ---------------------------------------------------
__device__ __forceinline__ float wred(float x) {
    x += __shfl_xor_sync(0xffffffffu, x, 16);
    x += __shfl_xor_sync(0xffffffffu, x, 8);
    x += __shfl_xor_sync(0xffffffffu, x, 4);
    x += __shfl_xor_sync(0xffffffffu, x, 2);
    x += __shfl_xor_sync(0xffffffffu, x, 1);
    return x;
}

__device__ __forceinline__ unsigned f2tf(float x) {
    unsigned u;
    asm("cvt.rna.tf32.f32 %0, %1;" : "=r"(u) : "f"(x));
    return u;
}

__device__ __forceinline__ void mma_tf32(float* d, const unsigned* a,
                                         unsigned b0, unsigned b1) {
    asm("mma.sync.aligned.m16n8k8.row.col.f32.tf32.tf32.f32 "
        "{%0,%1,%2,%3}, {%4,%5,%6,%7}, {%8,%9}, {%0,%1,%2,%3};"
        : "+f"(d[0]), "+f"(d[1]), "+f"(d[2]), "+f"(d[3])
        : "r"(a[0]), "r"(a[1]), "r"(a[2]), "r"(a[3]), "r"(b0), "r"(b1));
}

// ---------------- 1) zero counters + attn prep + W fragment swizzle ----------
__global__ __launch_bounds__(1024) void zero_prep(
        const float* __restrict__ W0,
        const float* __restrict__ Wnb, const float* __restrict__ bnb,
        const float* __restrict__ Wself, const float* __restrict__ bself,
        const float* __restrict__ Watt, const float* __restrict__ batt) {
    int i = blockIdx.x * 1024 + threadIdx.x;
    if (i < N_NODES) g_cnt[i] = 0;
    if (blockIdx.x == 0) {
        if (threadIdx.x == 0) g_total = 0;
        if (threadIdx.x < 32) {
            int j = threadIdx.x;
            float a = 0.f, b = 0.f;
#pragma unroll
            for (int q = 0; q < 8; ++q) {
                a += Wnb[j * 8 + q] * Watt[q];
                b += Wself[j * 8 + q] * Watt[8 + q];
            }
            g_att_a[j] = a;
            g_att_b[j] = b;
            if (j == 0) {
                float c = batt[0];
#pragma unroll
                for (int q = 0; q < 8; ++q)
                    c += bnb[q] * Watt[q] + bself[q] * Watt[8 + q];
                g_cst = c;
            }
        }
    } else if (blockIdx.x <= 8) {
        // W fragment swizzle: idx over 64*4*32 = 8192 entries
        int idx = (blockIdx.x - 1) * 1024 + threadIdx.x;
        int s = idx >> 7;            // k-step
        int t = (idx >> 5) & 3;      // n-tile
        int lane = idx & 31;
        int tig = lane & 3, gid = lane >> 2;
        float b0 = W0[(8 * s + tig) * 32 + 8 * t + gid];
        float b1 = W0[(8 * s + tig + 4) * 32 + 8 * t + gid];
        unsigned b0h = f2tf(b0), b1h = f2tf(b1);
        float b0hf = __uint_as_float(b0h), b1hf = __uint_as_float(b1h);
        unsigned b0l = f2tf(b0 - b0hf), b1l = f2tf(b1 - b1hf);
        g_wf[idx] = make_float4(b0hf, b1hf,
                                __uint_as_float(b0l), __uint_as_float(b1l));
    }
}

// ---------------- 2) in-degree count (4 edges / thread, int4) ----------------
__global__ void count_kernel(const int* __restrict__ eidx) {
    int t = blockIdx.x * blockDim.x + threadIdx.x;
    if (t >= N_EDGES / 4) return;
    int4 c = *(const int4*)(eidx + N_EDGES + t * 4);
    atomicAdd(&g_cnt[c.x], 1);
    atomicAdd(&g_cnt[c.y], 1);
    atomicAdd(&g_cnt[c.z], 1);
    atomicAdd(&g_cnt[c.w], 1);
}

// ---------------- 3) fused scan: block-local scan + atomic base --------------
__global__ __launch_bounds__(1024) void scan_fused() {
    __shared__ int sm[1024];
    __shared__ int sbase;
    int tid = threadIdx.x;
    int i = blockIdx.x * 1024 + tid;
    int v = (i < N_NODES) ? g_cnt[i] : 0;
    sm[tid] = v;
    __syncthreads();
    for (int o = 1; o < 1024; o <<= 1) {
        int t = (tid >= o) ? sm[tid - o] : 0;
        __syncthreads();
        sm[tid] += t;
        __syncthreads();
    }
    if (tid == 1023) sbase = atomicAdd(&g_total, sm[1023]);
    __syncthreads();
    if (i < N_NODES) {
        int o = sm[tid] - v + sbase;
        g_off[i] = o;
        g_cursor[i] = o;
        g_dinv0[i] = rsqrtf((float)v + 1.0f);
    }
}

// ---------------- 4) xw = dinv0 * (x @ W0)  (4-stage cp.async + tf32 mma) ----
// 128 threads / 128 rows per block; warp = 32 rows (2 m-tiles x 4 n-tiles).
// 4-stage ring of k-chunks of 16; wait_group 3 keeps 3 chunks (24 KB) in
// flight per block. Row stride 20 floats (80 B): 16B-aligned for cp.async,
// conflict-free bank pattern (gid*20+tig)%32 for fragment reads.
#define KCHUNK 16
#define KPAD   20
#define NCHUNK (IN_DIM / KCHUNK)   // 32
#define NSTAGE 4
__global__ __launch_bounds__(128) void gemm_xw(const float* __restrict__ x) {
    __shared__ float xs[NSTAGE][128][KPAD];   // 40960 B
    int tid = threadIdx.x;
    int lane = tid & 31;
    int warp = tid >> 5;            // 0..3
    int row0 = blockIdx.x * 128;
    int gid = lane >> 2, tig = lane & 3;
    int wrow = warp * 32;

    float acc[2][4][4];
#pragma unroll
    for (int m = 0; m < 2; ++m)
#pragma unroll
        for (int t = 0; t < 4; ++t)
#pragma unroll
            for (int r = 0; r < 4; ++r) acc[m][t][r] = 0.f;

    // issue chunk c into stage c % NSTAGE (coalesced: 4 consecutive 16B per row)
    auto issue = [&](int c) {
        int stg = c & (NSTAGE - 1);
        int k0 = c * KCHUNK;
#pragma unroll
        for (int it = 0; it < 4; ++it) {
            int idx = tid + it * 128;        // 0..511 float4 slots
            int rr = idx >> 2;               // 0..127
            int cc = (idx & 3) * 4;          // 0,4,8,12
            int grow = row0 + rr;
            if (grow >= N_NODES) grow = N_NODES - 1;   // clamp (stores guarded)
            const float* src = x + (size_t)grow * IN_DIM + k0 + cc;
            unsigned dst = (unsigned)__cvta_generic_to_shared(&xs[stg][rr][cc]);
            asm volatile("cp.async.ca.shared.global [%0], [%1], 16;"
                         :: "r"(dst), "l"(src));
        }
        asm volatile("cp.async.commit_group;");
    };

    issue(0); issue(1); issue(2); issue(3);

    for (int c = 0; c < NCHUNK; ++c) {
        asm volatile("cp.async.wait_group 3;");   // chunk c's group complete
        __syncthreads();
        int stg = c & (NSTAGE - 1);

#pragma unroll
        for (int ks = 0; ks < 2; ++ks) {
            int s = c * 2 + ks;              // global k-step 0..63
            int kk = ks * 8 + tig;
            float a[2][4];
            a[0][0] = xs[stg][wrow + gid     ][kk];
            a[0][1] = xs[stg][wrow + gid + 8 ][kk];
            a[0][2] = xs[stg][wrow + gid     ][kk + 4];
            a[0][3] = xs[stg][wrow + gid + 8 ][kk + 4];
            a[1][0] = xs[stg][wrow + gid + 16][kk];
            a[1][1] = xs[stg][wrow + gid + 24][kk];
            a[1][2] = xs[stg][wrow + gid + 16][kk + 4];
            a[1][3] = xs[stg][wrow + gid + 24][kk + 4];

            unsigned ah[2][4], al[2][4];
#pragma unroll
            for (int m = 0; m < 2; ++m)
#pragma unroll
                for (int j = 0; j < 4; ++j) {
                    unsigned h = f2tf(a[m][j]);
                    ah[m][j] = h;
                    al[m][j] = f2tf(a[m][j] - __uint_as_float(h));
                }

#pragma unroll
            for (int t = 0; t < 4; ++t) {
                float4 w = __ldg(&g_wf[(s * 4 + t) * 32 + lane]);
                unsigned bh0 = __float_as_uint(w.x), bh1 = __float_as_uint(w.y);
                unsigned bl0 = __float_as_uint(w.z), bl1 = __float_as_uint(w.w);
#pragma unroll
                for (int m = 0; m < 2; ++m) {
                    mma_tf32(acc[m][t], ah[m], bh0, bh1);
                    mma_tf32(acc[m][t], al[m], bh0, bh1);
                    mma_tf32(acc[m][t], ah[m], bl0, bl1);
                }
            }
        }
        __syncthreads();                     // stage free for reuse
        if (c + NSTAGE < NCHUNK) issue(c + NSTAGE);
        else asm volatile("cp.async.commit_group;");   // keep group count fixed
    }

    // epilogue: scale rows by rsqrt(indeg+1), store float2 pairs
#pragma unroll
    for (int m = 0; m < 2; ++m) {
        int rA = row0 + wrow + m * 16 + gid;
        int rB = rA + 8;
        if (rA < N_NODES) {
            float dA = rsqrtf((float)g_cnt[rA] + 1.f);
#pragma unroll
            for (int t = 0; t < 4; ++t) {
                int col = t * 8 + tig * 2;
                *(float2*)(g_xw + rA * 32 + col) =
                    make_float2(acc[m][t][0] * dA, acc[m][t][1] * dA);
            }
        }
        if (rB < N_NODES) {
            float dB = rsqrtf((float)g_cnt[rB] + 1.f);
#pragma unroll
            for (int t = 0; t < 4; ++t) {
                int col = t * 8 + tig * 2;
                *(float2*)(g_xw + rB * 32 + col) =
                    make_float2(acc[m][t][2] * dB, acc[m][t][3] * dB);
            }
        }
    }
}

// ---------------- 5) CSR fill (2 edges / thread, batched loads) --------------
__global__ void fill_kernel(const int* __restrict__ eidx) {
    int t = blockIdx.x * blockDim.x + threadIdx.x;
    if (t >= N_EDGES / 2) return;
    int2 r = *(const int2*)(eidx + t * 2);
    int2 c = *(const int2*)(eidx + N_EDGES + t * 2);
    int pos0 = atomicAdd(&g_cursor[c.x], 1);
    int pos1 = atomicAdd(&g_cursor[c.y], 1);
    g_src[pos0] = r.x;
    g_src[pos1] = r.y;
}

// ---------------- 6) conv0 + fused (hw, u, v) --------------------------------
__global__ __launch_bounds__(256) void conv0_kernel(const float* __restrict__ b0,
                                                    const float* __restrict__ W1) {
    __shared__ float hsm[8][32];
    int warp = (blockIdx.x * blockDim.x + threadIdx.x) >> 5;
    int lane = threadIdx.x & 31;
    int w = threadIdx.x >> 5;
    if (warp >= N_NODES) return;
    int node = warp;
    int s = g_off[node];
    int e = s + g_cnt[node];
    int g = lane >> 3;
    int f4 = (lane & 7) * 4;

    float4 acc;
    if (g == 0) acc = *(const float4*)(g_xw + node * 32 + f4);  // self (pre-scaled)
    else        acc = make_float4(0.f, 0.f, 0.f, 0.f);

    for (int p0 = s; p0 < e; p0 += 8) {
        int pA = p0 + g;
        int pB = p0 + 4 + g;
        int rA = (pA < e) ? g_src[pA] : -1;
        int rB = (pB < e) ? g_src[pB] : -1;
        if (rA >= 0) {
            float4 xv = *(const float4*)(g_xw + rA * 32 + f4);
            acc.x += xv.x; acc.y += xv.y; acc.z += xv.z; acc.w += xv.w;
        }
        if (rB >= 0) {
            float4 xv = *(const float4*)(g_xw + rB * 32 + f4);
            acc.x += xv.x; acc.y += xv.y; acc.z += xv.z; acc.w += xv.w;
        }
    }
    acc.x += __shfl_xor_sync(0xffffffffu, acc.x, 8);
    acc.y += __shfl_xor_sync(0xffffffffu, acc.y, 8);
    acc.z += __shfl_xor_sync(0xffffffffu, acc.z, 8);
    acc.w += __shfl_xor_sync(0xffffffffu, acc.w, 8);
    acc.x += __shfl_xor_sync(0xffffffffu, acc.x, 16);
    acc.y += __shfl_xor_sync(0xffffffffu, acc.y, 16);
    acc.z += __shfl_xor_sync(0xffffffffu, acc.z, 16);
    acc.w += __shfl_xor_sync(0xffffffffu, acc.w, 16);

    float dc = g_dinv0[node];
    if (g == 0) {
        hsm[w][f4 + 0] = dc * acc.x + __ldg(b0 + f4 + 0);
        hsm[w][f4 + 1] = dc * acc.y + __ldg(b0 + f4 + 1);
        hsm[w][f4 + 2] = dc * acc.z + __ldg(b0 + f4 + 2);
        hsm[w][f4 + 3] = dc * acc.w + __ldg(b0 + f4 + 3);
    }
    __syncwarp();

    float q = 0.f;
    if (lane < 8) {
#pragma unroll
        for (int j = 0; j < 32; ++j) q += hsm[w][j] * __ldg(W1 + j * 8 + lane);
        g_hw[node * 8 + lane] = q;
    } else if (lane == 8) {
#pragma unroll
        for (int j = 0; j < 32; ++j) q += hsm[w][j] * g_att_a[j];
        g_u[node] = q;
    } else if (lane == 9) {
#pragma unroll
        for (int j = 0; j < 32; ++j) q += hsm[w][j] * g_att_b[j];
        g_v[node] = q;
    }
}

// ---------------- 7) attention weights + dinv1 + hws -------------------------
__global__ __launch_bounds__(256) void attn_kernel() {
    int warp = (blockIdx.x * blockDim.x + threadIdx.x) >> 5;
    int lane = threadIdx.x & 31;
    if (warp >= N_NODES) return;
    int node = warp;
    float vc = g_v[node] + g_cst;
    int s = g_off[node];
    int e = s + g_cnt[node];
    float sum = 0.f;
    for (int p0 = s; p0 < e; p0 += 32) {
        int p = p0 + lane;
        float mw = 0.f;
        if (p < e) {
            int r = g_src[p];
            float wgt = fmaxf(g_u[r] + vc, 0.f);
            float m = fminf(ZETA / (1.f + __expf(-wgt)), 1.f);
            mw = m * wgt;
            g_mw[p] = mw;
        }
        sum += mw;
    }
    sum = wred(sum);
    float d1 = rsqrtf(sum + 1.0f);
    if (lane == 0) g_dinv1[node] = d1;
    if (lane < 8) g_hws[node * 8 + lane] = d1 * g_hw[node * 8 + lane];
}

// ---------------- 8) conv1 ---------------------------------------------------
__global__ __launch_bounds__(256) void conv1_kernel(const float* __restrict__ b1,
                                                    float* __restrict__ out) {
    int warp = (blockIdx.x * blockDim.x + threadIdx.x) >> 5;
    int lane = threadIdx.x & 31;
    if (warp >= N_NODES) return;
    int node = warp;
    int s = g_off[node];
    int e = s + g_cnt[node];
    int g = lane >> 3;
    int f = lane & 7;

    float acc = (g == 0) ? g_hws[node * 8 + f] : 0.f;  // self term

    for (int p0 = s; p0 < e; p0 += 8) {
        int pA = p0 + g;
        int pB = p0 + 4 + g;
        int rA = (pA < e) ? g_src[pA] : -1;
        int rB = (pB < e) ? g_src[pB] : -1;
        float cA = (pA < e) ? g_mw[pA] : 0.f;
        float cB = (pB < e) ? g_mw[pB] : 0.f;
        if (rA >= 0) acc += cA * g_hws[rA * 8 + f];
        if (rB >= 0) acc += cB * g_hws[rB * 8 + f];
    }
    acc += __shfl_xor_sync(0xffffffffu, acc, 8);
    acc += __shfl_xor_sync(0xffffffffu, acc, 16);

    if (lane < 8)
        out[node * 8 + lane] = g_dinv1[node] * acc + __ldg(b1 + lane);
}

// ---------------- launch -----------------------------------------------------
extern "C" void kernel_launch(void* const* d_in, const int* in_sizes, int n_in,
                              void* d_out, int out_size) {
    const float* x     = (const float*)d_in[0];
    const int*   eidx  = (const int*)  d_in[1];
    const float* W0    = (const float*)d_in[2];
    const float* b0    = (const float*)d_in[3];
    const float* W1    = (const float*)d_in[4];
    const float* b1    = (const float*)d_in[5];
    const float* Wnb   = (const float*)d_in[6];
    const float* bnb   = (const float*)d_in[7];
    const float* Wself = (const float*)d_in[8];
    const float* bself = (const float*)d_in[9];
    const float* Watt  = (const float*)d_in[10];
    const float* batt  = (const float*)d_in[11];
    float* out = (float*)d_out;

    zero_prep<<<NB_SCAN, 1024>>>(W0, Wnb, bnb, Wself, bself, Watt, batt);     // 0
    count_kernel<<<(N_EDGES / 4 + 255) / 256, 256>>>(eidx);                   // 1
    scan_fused<<<NB_SCAN, 1024>>>();                                          // 2
    gemm_xw<<<(N_NODES + 127) / 128, 128>>>(x);                               // 3 (profiled)
    fill_kernel<<<(N_EDGES / 2 + 255) / 256, 256>>>(eidx);                    // 4
    conv0_kernel<<<(N_NODES * 32 + 255) / 256, 256>>>(b0, W1);                // 5
    attn_kernel<<<(N_NODES * 32 + 255) / 256, 256>>>();                       // 6
    conv1_kernel<<<(N_NODES * 32 + 255) / 256, 256>>>(b1, out);               // 7
}

// round 13
// speedup vs baseline: 1.5611x; 1.0611x over previous
#include <cuda_runtime.h>

// PTDNet-GCN fused pipeline, round 12:
//  - GEMM: bf16 m16n8k16 mma with 3xBF16 (hi/lo) compensation — 4x less tensor
//    issue than 3xTF32 m16n8k8 (the measured floor). Same 4-stage cp.async ring.
//  - Everything else as the best-known configuration.

#define N_NODES 100000
#define N_EDGES 1600000
#define IN_DIM  512
#define H0      32
#define H1      8
#define ZETA    1.01f
#define NB_SCAN 98            // ceil(100000/1024)

// ---------------- scratch (static device memory) ----------------------------
__device__ float  g_xw[N_NODES * H0];     // dinv0[row] * (x @ W0)
__device__ float  g_hw[N_NODES * H1];     // h @ W1
__device__ float  g_hws[N_NODES * H1];    // dinv1[row] * hw
__device__ int    g_cnt[N_NODES];
__device__ int    g_off[N_NODES];         // bucket start (non-monotone partition)
__device__ int    g_cursor[N_NODES];
__device__ int    g_total;
__device__ int    g_src[N_EDGES];
__device__ float  g_mw[N_EDGES];
__device__ float  g_dinv0[N_NODES];
__device__ float  g_dinv1[N_NODES];
__device__ float  g_u[N_NODES];
__device__ float  g_v[N_NODES];
__device__ float  g_att_a[H0];
__device__ float  g_att_b[H0];
__device__ float  g_cst;
// W0 fragments: [32 k16-steps][4 n-tiles][32 lanes] -> (b0_hi, b1_hi, b0_lo, b1_lo)
// each element a bf16x2 register image
__device__ uint4  g_wf[32 * 4 * 32];

// ---------------- helpers ---------------------------------------------------
__device__ __forceinline__ float wred(float x) {
    x += __shfl_xor_sync(0xffffffffu, x, 16);
    x += __shfl_xor_sync(0xffffffffu, x, 8);
    x += __shfl_xor_sync(0xffffffffu, x, 4);
    x += __shfl_xor_sync(0xffffffffu, x, 2);
    x += __shfl_xor_sync(0xffffffffu, x, 1);
    return x;
}

// pack two floats into bf16x2 (lo -> low half, hi -> high half)
__device__ __forceinline__ unsigned packbf(float lo, float hi) {
    unsigned r;
    asm("cvt.rn.bf16x2.f32 %0, %1, %2;" : "=r"(r) : "f"(hi), "f"(lo));
    return r;
}
__device__ __forceinline__ float bflo(unsigned u) { return __uint_as_float(u << 16); }
__device__ __forceinline__ float bfhi(unsigned u) { return __uint_as_float(u & 0xffff0000u); }

// split (e0,e1) into bf16x2 hi part and bf16x2 lo (residual) part
__device__ __forceinline__ void bfsplit2(float e0, float e1,
                                         unsigned& h, unsigned& l) {
    h = packbf(e0, e1);
    l = packbf(e0 - bflo(h), e1 - bfhi(h));
}

__device__ __forceinline__ void mma_bf16(float* d, const unsigned* a,
                                         unsigned b0, unsigned b1) {
    asm("mma.sync.aligned.m16n8k16.row.col.f32.bf16.bf16.f32 "
        "{%0,%1,%2,%3}, {%4,%5,%6,%7}, {%8,%9}, {%0,%1,%2,%3};"
        : "+f"(d[0]), "+f"(d[1]), "+f"(d[2]), "+f"(d[3])
        : "r"(a[0]), "r"(a[1]), "r"(a[2]), "r"(a[3]), "r"(b0), "r"(b1));
}

// ---------------- 1) zero counters + attn prep + W fragment swizzle ----------
__global__ __launch_bounds__(1024) void zero_prep(
        const float* __restrict__ W0,
        const float* __restrict__ Wnb, const float* __restrict__ bnb,
        const float* __restrict__ Wself, const float* __restrict__ bself,
        const float* __restrict__ Watt, const float* __restrict__ batt) {
    int i = blockIdx.x * 1024 + threadIdx.x;
    if (i < N_NODES) g_cnt[i] = 0;
    if (blockIdx.x == 0) {
        if (threadIdx.x == 0) g_total = 0;
        if (threadIdx.x < 32) {
            int j = threadIdx.x;
            float a = 0.f, b = 0.f;
#pragma unroll
            for (int q = 0; q < 8; ++q) {
                a += Wnb[j * 8 + q] * Watt[q];
                b += Wself[j * 8 + q] * Watt[8 + q];
            }
            g_att_a[j] = a;
            g_att_b[j] = b;
            if (j == 0) {
                float c = batt[0];
#pragma unroll
                for (int q = 0; q < 8; ++q)
                    c += bnb[q] * Watt[q] + bself[q] * Watt[8 + q];
                g_cst = c;
            }
        }
    } else if (blockIdx.x <= 4) {
        // W fragment swizzle: idx over 32*4*32 = 4096 entries
        int idx = (blockIdx.x - 1) * 1024 + threadIdx.x;
        int s = idx >> 7;            // k16-step 0..31
        int t = (idx >> 5) & 3;      // n-tile
        int lane = idx & 31;
        int tig = lane & 3, gid = lane >> 2;
        int col = 8 * t + gid;
        float w00 = W0[(16 * s + 2 * tig) * 32 + col];
        float w01 = W0[(16 * s + 2 * tig + 1) * 32 + col];
        float w10 = W0[(16 * s + 2 * tig + 8) * 32 + col];
        float w11 = W0[(16 * s + 2 * tig + 9) * 32 + col];
        unsigned b0h, b0l, b1h, b1l;
        bfsplit2(w00, w01, b0h, b0l);
        bfsplit2(w10, w11, b1h, b1l);
        g_wf[idx] = make_uint4(b0h, b1h, b0l, b1l);
    }
}

// ---------------- 2) in-degree count (4 edges / thread, int4) ----------------
__global__ void count_kernel(const int* __restrict__ eidx) {
    int t = blockIdx.x * blockDim.x + threadIdx.x;
    if (t >= N_EDGES / 4) return;
    int4 c = *(const int4*)(eidx + N_EDGES + t * 4);
    atomicAdd(&g_cnt[c.x], 1);
    atomicAdd(&g_cnt[c.y], 1);
    atomicAdd(&g_cnt[c.z], 1);
    atomicAdd(&g_cnt[c.w], 1);
}

// ---------------- 3) fused scan: block-local scan + atomic base --------------
__global__ __launch_bounds__(1024) void scan_fused() {
    __shared__ int sm[1024];
    __shared__ int sbase;
    int tid = threadIdx.x;
    int i = blockIdx.x * 1024 + tid;
    int v = (i < N_NODES) ? g_cnt[i] : 0;
    sm[tid] = v;
    __syncthreads();
    for (int o = 1; o < 1024; o <<= 1) {
        int t = (tid >= o) ? sm[tid - o] : 0;
        __syncthreads();
        sm[tid] += t;
        __syncthreads();
    }
    if (tid == 1023) sbase = atomicAdd(&g_total, sm[1023]);
    __syncthreads();
    if (i < N_NODES) {
        int o = sm[tid] - v + sbase;
        g_off[i] = o;
        g_cursor[i] = o;
        g_dinv0[i] = rsqrtf((float)v + 1.0f);
    }
}

// ---------------- 4) xw = dinv0 * (x @ W0)  (cp.async + bf16 mma 3x) ---------
// 128 threads / 128 rows per block; warp = 32 rows (2 m-tiles x 4 n-tiles).
// 4-stage ring of k-chunks of 16 (= one m16n8k16 step each); wait_group 3.
// Row stride 20 floats (80 B): 16B-aligned for cp.async; float2 frag reads.
#define KCHUNK 16
#define KPAD   20
#define NCHUNK (IN_DIM / KCHUNK)   // 32
#define NSTAGE 4
__global__ __launch_bounds__(128) void gemm_xw(const float* __restrict__ x) {
    __shared__ float xs[NSTAGE][128][KPAD];   // 40960 B
    int tid = threadIdx.x;
    int lane = tid & 31;
    int warp = tid >> 5;            // 0..3
    int row0 = blockIdx.x * 128;
    int gid = lane >> 2, tig = lane & 3;
    int wrow = warp * 32;

    float acc[2][4][4];
#pragma unroll
    for (int m = 0; m < 2; ++m)
#pragma unroll
        for (int t = 0; t < 4; ++t)
#pragma unroll
            for (int r = 0; r < 4; ++r) acc[m][t][r] = 0.f;

    // issue chunk c into stage c % NSTAGE (coalesced: 4 consecutive 16B per row)
    auto issue = [&](int c) {
        int stg = c & (NSTAGE - 1);
        int k0 = c * KCHUNK;
#pragma unroll
        for (int it = 0; it < 4; ++it) {
            int idx = tid + it * 128;        // 0..511 float4 slots
            int rr = idx >> 2;               // 0..127
            int cc = (idx & 3) * 4;          // 0,4,8,12
            int grow = row0 + rr;
            if (grow >= N_NODES) grow = N_NODES - 1;   // clamp (stores guarded)
            const float* src = x + (size_t)grow * IN_DIM + k0 + cc;
            unsigned dst = (unsigned)__cvta_generic_to_shared(&xs[stg][rr][cc]);
            asm volatile("cp.async.ca.shared.global [%0], [%1], 16;"
                         :: "r"(dst), "l"(src));
        }
        asm volatile("cp.async.commit_group;");
    };

    issue(0); issue(1); issue(2); issue(3);

    for (int c = 0; c < NCHUNK; ++c) {
        asm volatile("cp.async.wait_group 3;");   // chunk c's group complete
        __syncthreads();
        int stg = c & (NSTAGE - 1);

        // A fragments for k16-step c: rows {gid,+8,+16,+24}, cols {2tig,+1} & {+8,+9}
        float2 p[2][4];
        p[0][0] = *(const float2*)&xs[stg][wrow + gid     ][2 * tig];
        p[0][1] = *(const float2*)&xs[stg][wrow + gid + 8 ][2 * tig];
        p[0][2] = *(const float2*)&xs[stg][wrow + gid     ][2 * tig + 8];
        p[0][3] = *(const float2*)&xs[stg][wrow + gid + 8 ][2 * tig + 8];
        p[1][0] = *(const float2*)&xs[stg][wrow + gid + 16][2 * tig];
        p[1][1] = *(const float2*)&xs[stg][wrow + gid + 24][2 * tig];
        p[1][2] = *(const float2*)&xs[stg][wrow + gid + 16][2 * tig + 8];
        p[1][3] = *(const float2*)&xs[stg][wrow + gid + 24][2 * tig + 8];

        unsigned ah[2][4], al[2][4];
#pragma unroll
        for (int m = 0; m < 2; ++m)
#pragma unroll
            for (int j = 0; j < 4; ++j)
                bfsplit2(p[m][j].x, p[m][j].y, ah[m][j], al[m][j]);

#pragma unroll
        for (int t = 0; t < 4; ++t) {
            uint4 w = __ldg(&g_wf[(c * 4 + t) * 32 + lane]);
#pragma unroll
            for (int m = 0; m < 2; ++m) {
                mma_bf16(acc[m][t], ah[m], w.x, w.y);   // ah*bh
                mma_bf16(acc[m][t], al[m], w.x, w.y);   // al*bh
                mma_bf16(acc[m][t], ah[m], w.z, w.w);   // ah*bl
            }
        }
        __syncthreads();                     // stage free for reuse
        if (c + NSTAGE < NCHUNK) issue(c + NSTAGE);
        else asm volatile("cp.async.commit_group;");   // keep group count fixed
    }

    // epilogue: scale rows by rsqrt(indeg+1), store float2 pairs
#pragma unroll
    for (int m = 0; m < 2; ++m) {
        int rA = row0 + wrow + m * 16 + gid;
        int rB = rA + 8;
        if (rA < N_NODES) {
            float dA = rsqrtf((float)g_cnt[rA] + 1.f);
#pragma unroll
            for (int t = 0; t < 4; ++t) {
                int col = t * 8 + tig * 2;
                *(float2*)(g_xw + rA * 32 + col) =
                    make_float2(acc[m][t][0] * dA, acc[m][t][1] * dA);
            }
        }
        if (rB < N_NODES) {
            float dB = rsqrtf((float)g_cnt[rB] + 1.f);
#pragma unroll
            for (int t = 0; t < 4; ++t) {
                int col = t * 8 + tig * 2;
                *(float2*)(g_xw + rB * 32 + col) =
                    make_float2(acc[m][t][2] * dB, acc[m][t][3] * dB);
            }
        }
    }
}

// ---------------- 5) CSR fill (2 edges / thread, batched loads) --------------
__global__ void fill_kernel(const int* __restrict__ eidx) {
    int t = blockIdx.x * blockDim.x + threadIdx.x;
    if (t >= N_EDGES / 2) return;
    int2 r = *(const int2*)(eidx + t * 2);
    int2 c = *(const int2*)(eidx + N_EDGES + t * 2);
    int pos0 = atomicAdd(&g_cursor[c.x], 1);
    int pos1 = atomicAdd(&g_cursor[c.y], 1);
    g_src[pos0] = r.x;
    g_src[pos1] = r.y;
}

// ---------------- 6) conv0 + fused (hw, u, v) --------------------------------
__global__ __launch_bounds__(256) void conv0_kernel(const float* __restrict__ b0,
                                                    const float* __restrict__ W1) {
    __shared__ float hsm[8][32];
    int warp = (blockIdx.x * blockDim.x + threadIdx.x) >> 5;
    int lane = threadIdx.x & 31;
    int w = threadIdx.x >> 5;
    if (warp >= N_NODES) return;
    int node = warp;
    int s = g_off[node];
    int e = s + g_cnt[node];
    int g = lane >> 3;
    int f4 = (lane & 7) * 4;

    float4 acc;
    if (g == 0) acc = *(const float4*)(g_xw + node * 32 + f4);  // self (pre-scaled)
    else        acc = make_float4(0.f, 0.f, 0.f, 0.f);

    for (int p0 = s; p0 < e; p0 += 8) {
        int pA = p0 + g;
        int pB = p0 + 4 + g;
        int rA = (pA < e) ? g_src[pA] : -1;
        int rB = (pB < e) ? g_src[pB] : -1;
        if (rA >= 0) {
            float4 xv = *(const float4*)(g_xw + rA * 32 + f4);
            acc.x += xv.x; acc.y += xv.y; acc.z += xv.z; acc.w += xv.w;
        }
        if (rB >= 0) {
            float4 xv = *(const float4*)(g_xw + rB * 32 + f4);
            acc.x += xv.x; acc.y += xv.y; acc.z += xv.z; acc.w += xv.w;
        }
    }
    acc.x += __shfl_xor_sync(0xffffffffu, acc.x, 8);
    acc.y += __shfl_xor_sync(0xffffffffu, acc.y, 8);
    acc.z += __shfl_xor_sync(0xffffffffu, acc.z, 8);
    acc.w += __shfl_xor_sync(0xffffffffu, acc.w, 8);
    acc.x += __shfl_xor_sync(0xffffffffu, acc.x, 16);
    acc.y += __shfl_xor_sync(0xffffffffu, acc.y, 16);
    acc.z += __shfl_xor_sync(0xffffffffu, acc.z, 16);
    acc.w += __shfl_xor_sync(0xffffffffu, acc.w, 16);

    float dc = g_dinv0[node];
    if (g == 0) {
        hsm[w][f4 + 0] = dc * acc.x + __ldg(b0 + f4 + 0);
        hsm[w][f4 + 1] = dc * acc.y + __ldg(b0 + f4 + 1);
        hsm[w][f4 + 2] = dc * acc.z + __ldg(b0 + f4 + 2);
        hsm[w][f4 + 3] = dc * acc.w + __ldg(b0 + f4 + 3);
    }
    __syncwarp();

    float q = 0.f;
    if (lane < 8) {
#pragma unroll
        for (int j = 0; j < 32; ++j) q += hsm[w][j] * __ldg(W1 + j * 8 + lane);
        g_hw[node * 8 + lane] = q;
    } else if (lane == 8) {
#pragma unroll
        for (int j = 0; j < 32; ++j) q += hsm[w][j] * g_att_a[j];
        g_u[node] = q;
    } else if (lane == 9) {
#pragma unroll
        for (int j = 0; j < 32; ++j) q += hsm[w][j] * g_att_b[j];
        g_v[node] = q;
    }
}

// ---------------- 7) attention weights + dinv1 + hws -------------------------
__global__ __launch_bounds__(256) void attn_kernel() {
    int warp = (blockIdx.x * blockDim.x + threadIdx.x) >> 5;
    int lane = threadIdx.x & 31;
    if (warp >= N_NODES) return;
    int node = warp;
    float vc = g_v[node] + g_cst;
    int s = g_off[node];
    int e = s + g_cnt[node];
    float sum = 0.f;
    for (int p0 = s; p0 < e; p0 += 32) {
        int p = p0 + lane;
        float mw = 0.f;
        if (p < e) {
            int r = g_src[p];
            float wgt = fmaxf(g_u[r] + vc, 0.f);
            float m = fminf(ZETA / (1.f + __expf(-wgt)), 1.f);
            mw = m * wgt;
            g_mw[p] = mw;
        }
        sum += mw;
    }
    sum = wred(sum);
    float d1 = rsqrtf(sum + 1.0f);
    if (lane == 0) g_dinv1[node] = d1;
    if (lane < 8) g_hws[node * 8 + lane] = d1 * g_hw[node * 8 + lane];
}

// ---------------- 8) conv1 ---------------------------------------------------
__global__ __launch_bounds__(256) void conv1_kernel(const float* __restrict__ b1,
                                                    float* __restrict__ out) {
    int warp = (blockIdx.x * blockDim.x + threadIdx.x) >> 5;
    int lane = threadIdx.x & 31;
    if (warp >= N_NODES) return;
    int node = warp;
    int s = g_off[node];
    int e = s + g_cnt[node];
    int g = lane >> 3;
    int f = lane & 7;

    float acc = (g == 0) ? g_hws[node * 8 + f] : 0.f;  // self term

    for (int p0 = s; p0 < e; p0 += 8) {
        int pA = p0 + g;
        int pB = p0 + 4 + g;
        int rA = (pA < e) ? g_src[pA] : -1;
        int rB = (pB < e) ? g_src[pB] : -1;
        float cA = (pA < e) ? g_mw[pA] : 0.f;
        float cB = (pB < e) ? g_mw[pB] : 0.f;
        if (rA >= 0) acc += cA * g_hws[rA * 8 + f];
        if (rB >= 0) acc += cB * g_hws[rB * 8 + f];
    }
    acc += __shfl_xor_sync(0xffffffffu, acc, 8);
    acc += __shfl_xor_sync(0xffffffffu, acc, 16);

    if (lane < 8)
        out[node * 8 + lane] = g_dinv1[node] * acc + __ldg(b1 + lane);
}

// ---------------- launch -----------------------------------------------------
extern "C" void kernel_launch(void* const* d_in, const int* in_sizes, int n_in,
                              void* d_out, int out_size) {
    const float* x     = (const float*)d_in[0];
    const int*   eidx  = (const int*)  d_in[1];
    const float* W0    = (const float*)d_in[2];
    const float* b0    = (const float*)d_in[3];
    const float* W1    = (const float*)d_in[4];
    const float* b1    = (const float*)d_in[5];
    const float* Wnb   = (const float*)d_in[6];
    const float* bnb   = (const float*)d_in[7];
    const float* Wself = (const float*)d_in[8];
    const float* bself = (const float*)d_in[9];
    const float* Watt  = (const float*)d_in[10];
    const float* batt  = (const float*)d_in[11];
    float* out = (float*)d_out;

    zero_prep<<<NB_SCAN, 1024>>>(W0, Wnb, bnb, Wself, bself, Watt, batt);     // 0
    count_kernel<<<(N_EDGES / 4 + 255) / 256, 256>>>(eidx);                   // 1
    scan_fused<<<NB_SCAN, 1024>>>();                                          // 2
    gemm_xw<<<(N_NODES + 127) / 128, 128>>>(x);                               // 3 (profiled)
    fill_kernel<<<(N_EDGES / 2 + 255) / 256, 256>>>(eidx);                    // 4
    conv0_kernel<<<(N_NODES * 32 + 255) / 256, 256>>>(b0, W1);                // 5
    attn_kernel<<<(N_NODES * 32 + 255) / 256, 256>>>();                       // 6
    conv1_kernel<<<(N_NODES * 32 + 255) / 256, 256>>>(b1, out);               // 7
}

// round 14
// speedup vs baseline: 1.7446x; 1.1175x over previous
#include <cuda_runtime.h>

// PTDNet-GCN fused pipeline, round 13:
//  - GEMM: bf16 m16n8k16 3xBF16 (as R12, proven) with a 3-stage cp.async ring,
//    ONE __syncthreads per chunk (cutlass ordering), __launch_bounds__(128,6)
//    -> 6 resident blocks/SM (was 5), 96 KB/SM in flight.
//  - Everything else as the best-known configuration.

#define N_NODES 100000
#define N_EDGES 1600000
#define IN_DIM  512
#define H0      32
#define H1      8
#define ZETA    1.01f
#define NB_SCAN 98            // ceil(100000/1024)

// ---------------- scratch (static device memory) ----------------------------
__device__ float  g_xw[N_NODES * H0];     // dinv0[row] * (x @ W0)
__device__ float  g_hw[N_NODES * H1];     // h @ W1
__device__ float  g_hws[N_NODES * H1];    // dinv1[row] * hw
__device__ int    g_cnt[N_NODES];
__device__ int    g_off[N_NODES];         // bucket start (non-monotone partition)
__device__ int    g_cursor[N_NODES];
__device__ int    g_total;
__device__ int    g_src[N_EDGES];
__device__ float  g_mw[N_EDGES];
__device__ float  g_dinv0[N_NODES];
__device__ float  g_dinv1[N_NODES];
__device__ float  g_u[N_NODES];
__device__ float  g_v[N_NODES];
__device__ float  g_att_a[H0];
__device__ float  g_att_b[H0];
__device__ float  g_cst;
// W0 fragments: [32 k16-steps][4 n-tiles][32 lanes] -> (b0_hi, b1_hi, b0_lo, b1_lo)
__device__ uint4  g_wf[32 * 4 * 32];

// ---------------- helpers ---------------------------------------------------
__device__ __forceinline__ float wred(float x) {
    x += __shfl_xor_sync(0xffffffffu, x, 16);
    x += __shfl_xor_sync(0xffffffffu, x, 8);
    x += __shfl_xor_sync(0xffffffffu, x, 4);
    x += __shfl_xor_sync(0xffffffffu, x, 2);
    x += __shfl_xor_sync(0xffffffffu, x, 1);
    return x;
}

// pack two floats into bf16x2 (e0 -> low half, e1 -> high half)
__device__ __forceinline__ unsigned packbf(float lo, float hi) {
    unsigned r;
    asm("cvt.rn.bf16x2.f32 %0, %1, %2;" : "=r"(r) : "f"(hi), "f"(lo));
    return r;
}
__device__ __forceinline__ float bflo(unsigned u) { return __uint_as_float(u << 16); }
__device__ __forceinline__ float bfhi(unsigned u) { return __uint_as_float(u & 0xffff0000u); }

__device__ __forceinline__ void bfsplit2(float e0, float e1,
                                         unsigned& h, unsigned& l) {
    h = packbf(e0, e1);
    l = packbf(e0 - bflo(h), e1 - bfhi(h));
}

__device__ __forceinline__ void mma_bf16(float* d, const unsigned* a,
                                         unsigned b0, unsigned b1) {
    asm("mma.sync.aligned.m16n8k16.row.col.f32.bf16.bf16.f32 "
        "{%0,%1,%2,%3}, {%4,%5,%6,%7}, {%8,%9}, {%0,%1,%2,%3};"
        : "+f"(d[0]), "+f"(d[1]), "+f"(d[2]), "+f"(d[3])
        : "r"(a[0]), "r"(a[1]), "r"(a[2]), "r"(a[3]), "r"(b0), "r"(b1));
}

// ---------------- 1) zero counters + attn prep + W fragment swizzle ----------
__global__ __launch_bounds__(1024) void zero_prep(
        const float* __restrict__ W0,
        const float* __restrict__ Wnb, const float* __restrict__ bnb,
        const float* __restrict__ Wself, const float* __restrict__ bself,
        const float* __restrict__ Watt, const float* __restrict__ batt) {
    int i = blockIdx.x * 1024 + threadIdx.x;
    if (i < N_NODES) g_cnt[i] = 0;
    if (blockIdx.x == 0) {
        if (threadIdx.x == 0) g_total = 0;
        if (threadIdx.x < 32) {
            int j = threadIdx.x;
            float a = 0.f, b = 0.f;
#pragma unroll
            for (int q = 0; q < 8; ++q) {
                a += Wnb[j * 8 + q] * Watt[q];
                b += Wself[j * 8 + q] * Watt[8 + q];
            }
            g_att_a[j] = a;
            g_att_b[j] = b;
            if (j == 0) {
                float c = batt[0];
#pragma unroll
                for (int q = 0; q < 8; ++q)
                    c += bnb[q] * Watt[q] + bself[q] * Watt[8 + q];
                g_cst = c;
            }
        }
    } else if (blockIdx.x <= 4) {
        // W fragment swizzle: idx over 32*4*32 = 4096 entries
        int idx = (blockIdx.x - 1) * 1024 + threadIdx.x;
        int s = idx >> 7;            // k16-step 0..31
        int t = (idx >> 5) & 3;      // n-tile
        int lane = idx & 31;
        int tig = lane & 3, gid = lane >> 2;
        int col = 8 * t + gid;
        float w00 = W0[(16 * s + 2 * tig) * 32 + col];
        float w01 = W0[(16 * s + 2 * tig + 1) * 32 + col];
        float w10 = W0[(16 * s + 2 * tig + 8) * 32 + col];
        float w11 = W0[(16 * s + 2 * tig + 9) * 32 + col];
        unsigned b0h, b0l, b1h, b1l;
        bfsplit2(w00, w01, b0h, b0l);
        bfsplit2(w10, w11, b1h, b1l);
        g_wf[idx] = make_uint4(b0h, b1h, b0l, b1l);
    }
}

// ---------------- 2) in-degree count (4 edges / thread, int4) ----------------
__global__ void count_kernel(const int* __restrict__ eidx) {
    int t = blockIdx.x * blockDim.x + threadIdx.x;
    if (t >= N_EDGES / 4) return;
    int4 c = *(const int4*)(eidx + N_EDGES + t * 4);
    atomicAdd(&g_cnt[c.x], 1);
    atomicAdd(&g_cnt[c.y], 1);
    atomicAdd(&g_cnt[c.z], 1);
    atomicAdd(&g_cnt[c.w], 1);
}

// ---------------- 3) fused scan: block-local scan + atomic base --------------
__global__ __launch_bounds__(1024) void scan_fused() {
    __shared__ int sm[1024];
    __shared__ int sbase;
    int tid = threadIdx.x;
    int i = blockIdx.x * 1024 + tid;
    int v = (i < N_NODES) ? g_cnt[i] : 0;
    sm[tid] = v;
    __syncthreads();
    for (int o = 1; o < 1024; o <<= 1) {
        int t = (tid >= o) ? sm[tid - o] : 0;
        __syncthreads();
        sm[tid] += t;
        __syncthreads();
    }
    if (tid == 1023) sbase = atomicAdd(&g_total, sm[1023]);
    __syncthreads();
    if (i < N_NODES) {
        int o = sm[tid] - v + sbase;
        g_off[i] = o;
        g_cursor[i] = o;
        g_dinv0[i] = rsqrtf((float)v + 1.0f);
    }
}

// ---------------- 4) xw = dinv0 * (x @ W0)  (3-stage cp.async + bf16 mma) ----
// 128 threads / 128 rows per block; warp = 32 rows (2 m-tiles x 4 n-tiles).
// 3-stage ring, one __syncthreads per chunk, __launch_bounds__(128,6) for
// 6 resident blocks/SM. Row stride 20 floats (80 B, 16B-aligned).
#define KCHUNK 16
#define KPAD   20
#define NCHUNK (IN_DIM / KCHUNK)   // 32
#define NSTAGE 3
__global__ __launch_bounds__(128, 6) void gemm_xw(const float* __restrict__ x) {
    __shared__ float xs[NSTAGE][128][KPAD];   // 30720 B
    int tid = threadIdx.x;
    int lane = tid & 31;
    int warp = tid >> 5;            // 0..3
    int row0 = blockIdx.x * 128;
    int gid = lane >> 2, tig = lane & 3;
    int wrow = warp * 32;

    float acc[2][4][4];
#pragma unroll
    for (int m = 0; m < 2; ++m)
#pragma unroll
        for (int t = 0; t < 4; ++t)
#pragma unroll
            for (int r = 0; r < 4; ++r) acc[m][t][r] = 0.f;

    // issue chunk c into stage c % NSTAGE (coalesced: 4 consecutive 16B per row)
    auto issue = [&](int c) {
        int stg = c % NSTAGE;
        int k0 = c * KCHUNK;
#pragma unroll
        for (int it = 0; it < 4; ++it) {
            int idx = tid + it * 128;        // 0..511 float4 slots
            int rr = idx >> 2;               // 0..127
            int cc = (idx & 3) * 4;          // 0,4,8,12
            int grow = row0 + rr;
            if (grow >= N_NODES) grow = N_NODES - 1;   // clamp (stores guarded)
            const float* src = x + (size_t)grow * IN_DIM + k0 + cc;
            unsigned dst = (unsigned)__cvta_generic_to_shared(&xs[stg][rr][cc]);
            asm volatile("cp.async.ca.shared.global [%0], [%1], 16;"
                         :: "r"(dst), "l"(src));
        }
        asm volatile("cp.async.commit_group;");
    };

    issue(0); issue(1);

    for (int c = 0; c < NCHUNK; ++c) {
        // pending groups at this point: {c, c+1} (invariant kept by tail
        // empty commits) -> wait_group 1 retires chunk c.
        asm volatile("cp.async.wait_group 1;");
        __syncthreads();   // also: every warp finished compute(c-1) -> stage
                           // (c-1)%3 == (c+2)%3 is free for reuse
        if (c + 2 < NCHUNK) issue(c + 2);
        else asm volatile("cp.async.commit_group;");   // keep 2 pending groups

        int stg = c % NSTAGE;

        // A fragments for k16-step c: rows {gid,+8,+16,+24}, cols {2tig,+1} & {+8,+9}
        float2 p[2][4];
        p[0][0] = *(const float2*)&xs[stg][wrow + gid     ][2 * tig];
        p[0][1] = *(const float2*)&xs[stg][wrow + gid + 8 ][2 * tig];
        p[0][2] = *(const float2*)&xs[stg][wrow + gid     ][2 * tig + 8];
        p[0][3] = *(const float2*)&xs[stg][wrow + gid + 8 ][2 * tig + 8];
        p[1][0] = *(const float2*)&xs[stg][wrow + gid + 16][2 * tig];
        p[1][1] = *(const float2*)&xs[stg][wrow + gid + 24][2 * tig];
        p[1][2] = *(const float2*)&xs[stg][wrow + gid + 16][2 * tig + 8];
        p[1][3] = *(const float2*)&xs[stg][wrow + gid + 24][2 * tig + 8];

        unsigned ah[2][4], al[2][4];
#pragma unroll
        for (int m = 0; m < 2; ++m)
#pragma unroll
            for (int j = 0; j < 4; ++j)
                bfsplit2(p[m][j].x, p[m][j].y, ah[m][j], al[m][j]);

#pragma unroll
        for (int t = 0; t < 4; ++t) {
            uint4 w = __ldg(&g_wf[(c * 4 + t) * 32 + lane]);
#pragma unroll
            for (int m = 0; m < 2; ++m) {
                mma_bf16(acc[m][t], ah[m], w.x, w.y);   // ah*bh
                mma_bf16(acc[m][t], al[m], w.x, w.y);   // al*bh
                mma_bf16(acc[m][t], ah[m], w.z, w.w);   // ah*bl
            }
        }
    }

    // epilogue: scale rows by rsqrt(indeg+1), store float2 pairs
#pragma unroll
    for (int m = 0; m < 2; ++m) {
        int rA = row0 + wrow + m * 16 + gid;
        int rB = rA + 8;
        if (rA < N_NODES) {
            float dA = rsqrtf((float)g_cnt[rA] + 1.f);
#pragma unroll
            for (int t = 0; t < 4; ++t) {
                int col = t * 8 + tig * 2;
                *(float2*)(g_xw + rA * 32 + col) =
                    make_float2(acc[m][t][0] * dA, acc[m][t][1] * dA);
            }
        }
        if (rB < N_NODES) {
            float dB = rsqrtf((float)g_cnt[rB] + 1.f);
#pragma unroll
            for (int t = 0; t < 4; ++t) {
                int col = t * 8 + tig * 2;
                *(float2*)(g_xw + rB * 32 + col) =
                    make_float2(acc[m][t][2] * dB, acc[m][t][3] * dB);
            }
        }
    }
}

// ---------------- 5) CSR fill (2 edges / thread, batched loads) --------------
__global__ void fill_kernel(const int* __restrict__ eidx) {
    int t = blockIdx.x * blockDim.x + threadIdx.x;
    if (t >= N_EDGES / 2) return;
    int2 r = *(const int2*)(eidx + t * 2);
    int2 c = *(const int2*)(eidx + N_EDGES + t * 2);
    int pos0 = atomicAdd(&g_cursor[c.x], 1);
    int pos1 = atomicAdd(&g_cursor[c.y], 1);
    g_src[pos0] = r.x;
    g_src[pos1] = r.y;
}

// ---------------- 6) conv0 + fused (hw, u, v) --------------------------------
__global__ __launch_bounds__(256) void conv0_kernel(const float* __restrict__ b0,
                                                    const float* __restrict__ W1) {
    __shared__ float hsm[8][32];
    int warp = (blockIdx.x * blockDim.x + threadIdx.x) >> 5;
    int lane = threadIdx.x & 31;
    int w = threadIdx.x >> 5;
    if (warp >= N_NODES) return;
    int node = warp;
    int s = g_off[node];
    int e = s + g_cnt[node];
    int g = lane >> 3;
    int f4 = (lane & 7) * 4;

    float4 acc;
    if (g == 0) acc = *(const float4*)(g_xw + node * 32 + f4);  // self (pre-scaled)
    else        acc = make_float4(0.f, 0.f, 0.f, 0.f);

    for (int p0 = s; p0 < e; p0 += 8) {
        int pA = p0 + g;
        int pB = p0 + 4 + g;
        int rA = (pA < e) ? g_src[pA] : -1;
        int rB = (pB < e) ? g_src[pB] : -1;
        if (rA >= 0) {
            float4 xv = *(const float4*)(g_xw + rA * 32 + f4);
            acc.x += xv.x; acc.y += xv.y; acc.z += xv.z; acc.w += xv.w;
        }
        if (rB >= 0) {
            float4 xv = *(const float4*)(g_xw + rB * 32 + f4);
            acc.x += xv.x; acc.y += xv.y; acc.z += xv.z; acc.w += xv.w;
        }
    }
    acc.x += __shfl_xor_sync(0xffffffffu, acc.x, 8);
    acc.y += __shfl_xor_sync(0xffffffffu, acc.y, 8);
    acc.z += __shfl_xor_sync(0xffffffffu, acc.z, 8);
    acc.w += __shfl_xor_sync(0xffffffffu, acc.w, 8);
    acc.x += __shfl_xor_sync(0xffffffffu, acc.x, 16);
    acc.y += __shfl_xor_sync(0xffffffffu, acc.y, 16);
    acc.z += __shfl_xor_sync(0xffffffffu, acc.z, 16);
    acc.w += __shfl_xor_sync(0xffffffffu, acc.w, 16);

    float dc = g_dinv0[node];
    if (g == 0) {
        hsm[w][f4 + 0] = dc * acc.x + __ldg(b0 + f4 + 0);
        hsm[w][f4 + 1] = dc * acc.y + __ldg(b0 + f4 + 1);
        hsm[w][f4 + 2] = dc * acc.z + __ldg(b0 + f4 + 2);
        hsm[w][f4 + 3] = dc * acc.w + __ldg(b0 + f4 + 3);
    }
    __syncwarp();

    float q = 0.f;
    if (lane < 8) {
#pragma unroll
        for (int j = 0; j < 32; ++j) q += hsm[w][j] * __ldg(W1 + j * 8 + lane);
        g_hw[node * 8 + lane] = q;
    } else if (lane == 8) {
#pragma unroll
        for (int j = 0; j < 32; ++j) q += hsm[w][j] * g_att_a[j];
        g_u[node] = q;
    } else if (lane == 9) {
#pragma unroll
        for (int j = 0; j < 32; ++j) q += hsm[w][j] * g_att_b[j];
        g_v[node] = q;
    }
}

// ---------------- 7) attention weights + dinv1 + hws -------------------------
__global__ __launch_bounds__(256) void attn_kernel() {
    int warp = (blockIdx.x * blockDim.x + threadIdx.x) >> 5;
    int lane = threadIdx.x & 31;
    if (warp >= N_NODES) return;
    int node = warp;
    float vc = g_v[node] + g_cst;
    int s = g_off[node];
    int e = s + g_cnt[node];
    float sum = 0.f;
    for (int p0 = s; p0 < e; p0 += 32) {
        int p = p0 + lane;
        float mw = 0.f;
        if (p < e) {
            int r = g_src[p];
            float wgt = fmaxf(g_u[r] + vc, 0.f);
            float m = fminf(ZETA / (1.f + __expf(-wgt)), 1.f);
            mw = m * wgt;
            g_mw[p] = mw;
        }
        sum += mw;
    }
    sum = wred(sum);
    float d1 = rsqrtf(sum + 1.0f);
    if (lane == 0) g_dinv1[node] = d1;
    if (lane < 8) g_hws[node * 8 + lane] = d1 * g_hw[node * 8 + lane];
}

// ---------------- 8) conv1 ---------------------------------------------------
__global__ __launch_bounds__(256) void conv1_kernel(const float* __restrict__ b1,
                                                    float* __restrict__ out) {
    int warp = (blockIdx.x * blockDim.x + threadIdx.x) >> 5;
    int lane = threadIdx.x & 31;
    if (warp >= N_NODES) return;
    int node = warp;
    int s = g_off[node];
    int e = s + g_cnt[node];
    int g = lane >> 3;
    int f = lane & 7;

    float acc = (g == 0) ? g_hws[node * 8 + f] : 0.f;  // self term

    for (int p0 = s; p0 < e; p0 += 8) {
        int pA = p0 + g;
        int pB = p0 + 4 + g;
        int rA = (pA < e) ? g_src[pA] : -1;
        int rB = (pB < e) ? g_src[pB] : -1;
        float cA = (pA < e) ? g_mw[pA] : 0.f;
        float cB = (pB < e) ? g_mw[pB] : 0.f;
        if (rA >= 0) acc += cA * g_hws[rA * 8 + f];
        if (rB >= 0) acc += cB * g_hws[rB * 8 + f];
    }
    acc += __shfl_xor_sync(0xffffffffu, acc, 8);
    acc += __shfl_xor_sync(0xffffffffu, acc, 16);

    if (lane < 8)
        out[node * 8 + lane] = g_dinv1[node] * acc + __ldg(b1 + lane);
}

// ---------------- launch -----------------------------------------------------
extern "C" void kernel_launch(void* const* d_in, const int* in_sizes, int n_in,
                              void* d_out, int out_size) {
    const float* x     = (const float*)d_in[0];
    const int*   eidx  = (const int*)  d_in[1];
    const float* W0    = (const float*)d_in[2];
    const float* b0    = (const float*)d_in[3];
    const float* W1    = (const float*)d_in[4];
    const float* b1    = (const float*)d_in[5];
    const float* Wnb   = (const float*)d_in[6];
    const float* bnb   = (const float*)d_in[7];
    const float* Wself = (const float*)d_in[8];
    const float* bself = (const float*)d_in[9];
    const float* Watt  = (const float*)d_in[10];
    const float* batt  = (const float*)d_in[11];
    float* out = (float*)d_out;

    zero_prep<<<NB_SCAN, 1024>>>(W0, Wnb, bnb, Wself, bself, Watt, batt);     // 0
    count_kernel<<<(N_EDGES / 4 + 255) / 256, 256>>>(eidx);                   // 1
    scan_fused<<<NB_SCAN, 1024>>>();                                          // 2
    gemm_xw<<<(N_NODES + 127) / 128, 128>>>(x);                               // 3 (profiled)
    fill_kernel<<<(N_EDGES / 2 + 255) / 256, 256>>>(eidx);                    // 4
    conv0_kernel<<<(N_NODES * 32 + 255) / 256, 256>>>(b0, W1);                // 5
    attn_kernel<<<(N_NODES * 32 + 255) / 256, 256>>>();                       // 6
    conv1_kernel<<<(N_NODES * 32 + 255) / 256, 256>>>(b1, out);               // 7
}

// round 15
// speedup vs baseline: 1.8725x; 1.0733x over previous
#include <cuda_runtime.h>

// PTDNet-GCN fused pipeline, round 14:
//  - CSR replaced by fixed-stride buckets (64 slots/node): fill does
//    count+placement in ONE kernel (atomicAdd on cnt = cursor). count_kernel
//    and scan_fused deleted. dinv0 computed in the gemm epilogue.
//  - GEMM: unchanged from R13 (bf16 3x, 3-stage cp.async, 1 sync, 6 blocks/SM).
//  - 6 launches total; conv0 now sits at profiled idx 3.

#define N_NODES 100000
#define N_EDGES 1600000
#define IN_DIM  512
#define H0      32
#define H1      8
#define ZETA    1.01f
#define NB_ZERO 98            // ceil(100000/1024)
#define DSHIFT  6             // 64 slots per node
#define DSTRIDE 64

// ---------------- scratch (static device memory) ----------------------------
__device__ float  g_xw[N_NODES * H0];     // dinv0[row] * (x @ W0)
__device__ float  g_hw[N_NODES * H1];     // h @ W1
__device__ float  g_hws[N_NODES * H1];    // dinv1[row] * hw
__device__ int    g_cnt[N_NODES];         // in-degree (built by fill)
__device__ int    g_src[N_NODES * DSTRIDE]; // bucketed source nodes
__device__ float  g_mw[N_NODES * DSTRIDE];  // masked edge weight (bucket order)
__device__ float  g_dinv0[N_NODES];
__device__ float  g_dinv1[N_NODES];
__device__ float  g_u[N_NODES];
__device__ float  g_v[N_NODES];
__device__ float  g_att_a[H0];
__device__ float  g_att_b[H0];
__device__ float  g_cst;
// W0 fragments: [32 k16-steps][4 n-tiles][32 lanes] -> (b0_hi, b1_hi, b0_lo, b1_lo)
__device__ uint4  g_wf[32 * 4 * 32];

// ---------------- helpers ---------------------------------------------------
__device__ __forceinline__ float wred(float x) {
    x += __shfl_xor_sync(0xffffffffu, x, 16);
    x += __shfl_xor_sync(0xffffffffu, x, 8);
    x += __shfl_xor_sync(0xffffffffu, x, 4);
    x += __shfl_xor_sync(0xffffffffu, x, 2);
    x += __shfl_xor_sync(0xffffffffu, x, 1);
    return x;
}

__device__ __forceinline__ unsigned packbf(float lo, float hi) {
    unsigned r;
    asm("cvt.rn.bf16x2.f32 %0, %1, %2;" : "=r"(r) : "f"(hi), "f"(lo));
    return r;
}
__device__ __forceinline__ float bflo(unsigned u) { return __uint_as_float(u << 16); }
__device__ __forceinline__ float bfhi(unsigned u) { return __uint_as_float(u & 0xffff0000u); }

__device__ __forceinline__ void bfsplit2(float e0, float e1,
                                         unsigned& h, unsigned& l) {
    h = packbf(e0, e1);
    l = packbf(e0 - bflo(h), e1 - bfhi(h));
}

__device__ __forceinline__ void mma_bf16(float* d, const unsigned* a,
                                         unsigned b0, unsigned b1) {
    asm("mma.sync.aligned.m16n8k16.row.col.f32.bf16.bf16.f32 "
        "{%0,%1,%2,%3}, {%4,%5,%6,%7}, {%8,%9}, {%0,%1,%2,%3};"
        : "+f"(d[0]), "+f"(d[1]), "+f"(d[2]), "+f"(d[3])
        : "r"(a[0]), "r"(a[1]), "r"(a[2]), "r"(a[3]), "r"(b0), "r"(b1));
}

// ---------------- 1) zero counters + attn prep + W fragment swizzle ----------
__global__ __launch_bounds__(1024) void zero_prep(
        const float* __restrict__ W0,
        const float* __restrict__ Wnb, const float* __restrict__ bnb,
        const float* __restrict__ Wself, const float* __restrict__ bself,
        const float* __restrict__ Watt, const float* __restrict__ batt) {
    int i = blockIdx.x * 1024 + threadIdx.x;
    if (i < N_NODES) g_cnt[i] = 0;
    if (blockIdx.x == 0) {
        if (threadIdx.x < 32) {
            int j = threadIdx.x;
            float a = 0.f, b = 0.f;
#pragma unroll
            for (int q = 0; q < 8; ++q) {
                a += Wnb[j * 8 + q] * Watt[q];
                b += Wself[j * 8 + q] * Watt[8 + q];
            }
            g_att_a[j] = a;
            g_att_b[j] = b;
            if (j == 0) {
                float c = batt[0];
#pragma unroll
                for (int q = 0; q < 8; ++q)
                    c += bnb[q] * Watt[q] + bself[q] * Watt[8 + q];
                g_cst = c;
            }
        }
    } else if (blockIdx.x <= 4) {
        // W fragment swizzle: idx over 32*4*32 = 4096 entries
        int idx = (blockIdx.x - 1) * 1024 + threadIdx.x;
        int s = idx >> 7;            // k16-step 0..31
        int t = (idx >> 5) & 3;      // n-tile
        int lane = idx & 31;
        int tig = lane & 3, gid = lane >> 2;
        int col = 8 * t + gid;
        float w00 = W0[(16 * s + 2 * tig) * 32 + col];
        float w01 = W0[(16 * s + 2 * tig + 1) * 32 + col];
        float w10 = W0[(16 * s + 2 * tig + 8) * 32 + col];
        float w11 = W0[(16 * s + 2 * tig + 9) * 32 + col];
        unsigned b0h, b0l, b1h, b1l;
        bfsplit2(w00, w01, b0h, b0l);
        bfsplit2(w10, w11, b1h, b1l);
        g_wf[idx] = make_uint4(b0h, b1h, b0l, b1l);
    }
}

// ---------------- 2) bucket fill: count + place in one pass ------------------
__global__ void fill_kernel(const int* __restrict__ eidx) {
    int t = blockIdx.x * blockDim.x + threadIdx.x;
    if (t >= N_EDGES / 2) return;
    int2 r = *(const int2*)(eidx + t * 2);
    int2 c = *(const int2*)(eidx + N_EDGES + t * 2);
    int p0 = atomicAdd(&g_cnt[c.x], 1);
    int p1 = atomicAdd(&g_cnt[c.y], 1);
    g_src[(c.x << DSHIFT) + p0] = r.x;
    g_src[(c.y << DSHIFT) + p1] = r.y;
}

// ---------------- 3) xw = dinv0 * (x @ W0)  (3-stage cp.async + bf16 mma) ----
// Unchanged from R13 except: also writes g_dinv0 (needs g_cnt -> after fill).
#define KCHUNK 16
#define KPAD   20
#define NCHUNK (IN_DIM / KCHUNK)   // 32
#define NSTAGE 3
__global__ __launch_bounds__(128, 6) void gemm_xw(const float* __restrict__ x) {
    __shared__ float xs[NSTAGE][128][KPAD];   // 30720 B
    int tid = threadIdx.x;
    int lane = tid & 31;
    int warp = tid >> 5;            // 0..3
    int row0 = blockIdx.x * 128;
    int gid = lane >> 2, tig = lane & 3;
    int wrow = warp * 32;

    float acc[2][4][4];
#pragma unroll
    for (int m = 0; m < 2; ++m)
#pragma unroll
        for (int t = 0; t < 4; ++t)
#pragma unroll
            for (int r = 0; r < 4; ++r) acc[m][t][r] = 0.f;

    auto issue = [&](int c) {
        int stg = c % NSTAGE;
        int k0 = c * KCHUNK;
#pragma unroll
        for (int it = 0; it < 4; ++it) {
            int idx = tid + it * 128;        // 0..511 float4 slots
            int rr = idx >> 2;               // 0..127
            int cc = (idx & 3) * 4;          // 0,4,8,12
            int grow = row0 + rr;
            if (grow >= N_NODES) grow = N_NODES - 1;   // clamp (stores guarded)
            const float* src = x + (size_t)grow * IN_DIM + k0 + cc;
            unsigned dst = (unsigned)__cvta_generic_to_shared(&xs[stg][rr][cc]);
            asm volatile("cp.async.ca.shared.global [%0], [%1], 16;"
                         :: "r"(dst), "l"(src));
        }
        asm volatile("cp.async.commit_group;");
    };

    issue(0); issue(1);

    for (int c = 0; c < NCHUNK; ++c) {
        asm volatile("cp.async.wait_group 1;");
        __syncthreads();
        if (c + 2 < NCHUNK) issue(c + 2);
        else asm volatile("cp.async.commit_group;");   // keep 2 pending groups

        int stg = c % NSTAGE;

        float2 p[2][4];
        p[0][0] = *(const float2*)&xs[stg][wrow + gid     ][2 * tig];
        p[0][1] = *(const float2*)&xs[stg][wrow + gid + 8 ][2 * tig];
        p[0][2] = *(const float2*)&xs[stg][wrow + gid     ][2 * tig + 8];
        p[0][3] = *(const float2*)&xs[stg][wrow + gid + 8 ][2 * tig + 8];
        p[1][0] = *(const float2*)&xs[stg][wrow + gid + 16][2 * tig];
        p[1][1] = *(const float2*)&xs[stg][wrow + gid + 24][2 * tig];
        p[1][2] = *(const float2*)&xs[stg][wrow + gid + 16][2 * tig + 8];
        p[1][3] = *(const float2*)&xs[stg][wrow + gid + 24][2 * tig + 8];

        unsigned ah[2][4], al[2][4];
#pragma unroll
        for (int m = 0; m < 2; ++m)
#pragma unroll
            for (int j = 0; j < 4; ++j)
                bfsplit2(p[m][j].x, p[m][j].y, ah[m][j], al[m][j]);

#pragma unroll
        for (int t = 0; t < 4; ++t) {
            uint4 w = __ldg(&g_wf[(c * 4 + t) * 32 + lane]);
#pragma unroll
            for (int m = 0; m < 2; ++m) {
                mma_bf16(acc[m][t], ah[m], w.x, w.y);   // ah*bh
                mma_bf16(acc[m][t], al[m], w.x, w.y);   // al*bh
                mma_bf16(acc[m][t], ah[m], w.z, w.w);   // ah*bl
            }
        }
    }

    // epilogue: dinv0 = rsqrt(indeg+1); write scaled rows + g_dinv0
#pragma unroll
    for (int m = 0; m < 2; ++m) {
        int rA = row0 + wrow + m * 16 + gid;
        int rB = rA + 8;
        if (rA < N_NODES) {
            float dA = rsqrtf((float)g_cnt[rA] + 1.f);
            if (tig == 0) g_dinv0[rA] = dA;
#pragma unroll
            for (int t = 0; t < 4; ++t) {
                int col = t * 8 + tig * 2;
                *(float2*)(g_xw + rA * 32 + col) =
                    make_float2(acc[m][t][0] * dA, acc[m][t][1] * dA);
            }
        }
        if (rB < N_NODES) {
            float dB = rsqrtf((float)g_cnt[rB] + 1.f);
            if (tig == 0) g_dinv0[rB] = dB;
#pragma unroll
            for (int t = 0; t < 4; ++t) {
                int col = t * 8 + tig * 2;
                *(float2*)(g_xw + rB * 32 + col) =
                    make_float2(acc[m][t][2] * dB, acc[m][t][3] * dB);
            }
        }
    }
}

// ---------------- 4) conv0 + fused (hw, u, v) --------------------------------
__global__ __launch_bounds__(256) void conv0_kernel(const float* __restrict__ b0,
                                                    const float* __restrict__ W1) {
    __shared__ float hsm[8][32];
    int warp = (blockIdx.x * blockDim.x + threadIdx.x) >> 5;
    int lane = threadIdx.x & 31;
    int w = threadIdx.x >> 5;
    if (warp >= N_NODES) return;
    int node = warp;
    int s = node << DSHIFT;
    int e = s + g_cnt[node];
    int g = lane >> 3;
    int f4 = (lane & 7) * 4;

    float4 acc;
    if (g == 0) acc = *(const float4*)(g_xw + node * 32 + f4);  // self (pre-scaled)
    else        acc = make_float4(0.f, 0.f, 0.f, 0.f);

    for (int p0 = s; p0 < e; p0 += 8) {
        int pA = p0 + g;
        int pB = p0 + 4 + g;
        int rA = (pA < e) ? g_src[pA] : -1;
        int rB = (pB < e) ? g_src[pB] : -1;
        if (rA >= 0) {
            float4 xv = *(const float4*)(g_xw + rA * 32 + f4);
            acc.x += xv.x; acc.y += xv.y; acc.z += xv.z; acc.w += xv.w;
        }
        if (rB >= 0) {
            float4 xv = *(const float4*)(g_xw + rB * 32 + f4);
            acc.x += xv.x; acc.y += xv.y; acc.z += xv.z; acc.w += xv.w;
        }
    }
    acc.x += __shfl_xor_sync(0xffffffffu, acc.x, 8);
    acc.y += __shfl_xor_sync(0xffffffffu, acc.y, 8);
    acc.z += __shfl_xor_sync(0xffffffffu, acc.z, 8);
    acc.w += __shfl_xor_sync(0xffffffffu, acc.w, 8);
    acc.x += __shfl_xor_sync(0xffffffffu, acc.x, 16);
    acc.y += __shfl_xor_sync(0xffffffffu, acc.y, 16);
    acc.z += __shfl_xor_sync(0xffffffffu, acc.z, 16);
    acc.w += __shfl_xor_sync(0xffffffffu, acc.w, 16);

    float dc = g_dinv0[node];
    if (g == 0) {
        hsm[w][f4 + 0] = dc * acc.x + __ldg(b0 + f4 + 0);
        hsm[w][f4 + 1] = dc * acc.y + __ldg(b0 + f4 + 1);
        hsm[w][f4 + 2] = dc * acc.z + __ldg(b0 + f4 + 2);
        hsm[w][f4 + 3] = dc * acc.w + __ldg(b0 + f4 + 3);
    }
    __syncwarp();

    float q = 0.f;
    if (lane < 8) {
#pragma unroll
        for (int j = 0; j < 32; ++j) q += hsm[w][j] * __ldg(W1 + j * 8 + lane);
        g_hw[node * 8 + lane] = q;
    } else if (lane == 8) {
#pragma unroll
        for (int j = 0; j < 32; ++j) q += hsm[w][j] * g_att_a[j];
        g_u[node] = q;
    } else if (lane == 9) {
#pragma unroll
        for (int j = 0; j < 32; ++j) q += hsm[w][j] * g_att_b[j];
        g_v[node] = q;
    }
}

// ---------------- 5) attention weights + dinv1 + hws -------------------------
__global__ __launch_bounds__(256) void attn_kernel() {
    int warp = (blockIdx.x * blockDim.x + threadIdx.x) >> 5;
    int lane = threadIdx.x & 31;
    if (warp >= N_NODES) return;
    int node = warp;
    float vc = g_v[node] + g_cst;
    int s = node << DSHIFT;
    int e = s + g_cnt[node];
    float sum = 0.f;
    for (int p0 = s; p0 < e; p0 += 32) {
        int p = p0 + lane;
        float mw = 0.f;
        if (p < e) {
            int r = g_src[p];
            float wgt = fmaxf(g_u[r] + vc, 0.f);
            float m = fminf(ZETA / (1.f + __expf(-wgt)), 1.f);
            mw = m * wgt;
            g_mw[p] = mw;
        }
        sum += mw;
    }
    sum = wred(sum);
    float d1 = rsqrtf(sum + 1.0f);
    if (lane == 0) g_dinv1[node] = d1;
    if (lane < 8) g_hws[node * 8 + lane] = d1 * g_hw[node * 8 + lane];
}

// ---------------- 6) conv1 ---------------------------------------------------
__global__ __launch_bounds__(256) void conv1_kernel(const float* __restrict__ b1,
                                                    float* __restrict__ out) {
    int warp = (blockIdx.x * blockDim.x + threadIdx.x) >> 5;
    int lane = threadIdx.x & 31;
    if (warp >= N_NODES) return;
    int node = warp;
    int s = node << DSHIFT;
    int e = s + g_cnt[node];
    int g = lane >> 3;
    int f = lane & 7;

    float acc = (g == 0) ? g_hws[node * 8 + f] : 0.f;  // self term

    for (int p0 = s; p0 < e; p0 += 8) {
        int pA = p0 + g;
        int pB = p0 + 4 + g;
        int rA = (pA < e) ? g_src[pA] : -1;
        int rB = (pB < e) ? g_src[pB] : -1;
        float cA = (pA < e) ? g_mw[pA] : 0.f;
        float cB = (pB < e) ? g_mw[pB] : 0.f;
        if (rA >= 0) acc += cA * g_hws[rA * 8 + f];
        if (rB >= 0) acc += cB * g_hws[rB * 8 + f];
    }
    acc += __shfl_xor_sync(0xffffffffu, acc, 8);
    acc += __shfl_xor_sync(0xffffffffu, acc, 16);

    if (lane < 8)
        out[node * 8 + lane] = g_dinv1[node] * acc + __ldg(b1 + lane);
}

// ---------------- launch -----------------------------------------------------
extern "C" void kernel_launch(void* const* d_in, const int* in_sizes, int n_in,
                              void* d_out, int out_size) {
    const float* x     = (const float*)d_in[0];
    const int*   eidx  = (const int*)  d_in[1];
    const float* W0    = (const float*)d_in[2];
    const float* b0    = (const float*)d_in[3];
    const float* W1    = (const float*)d_in[4];
    const float* b1    = (const float*)d_in[5];
    const float* Wnb   = (const float*)d_in[6];
    const float* bnb   = (const float*)d_in[7];
    const float* Wself = (const float*)d_in[8];
    const float* bself = (const float*)d_in[9];
    const float* Watt  = (const float*)d_in[10];
    const float* batt  = (const float*)d_in[11];
    float* out = (float*)d_out;

    zero_prep<<<NB_ZERO, 1024>>>(W0, Wnb, bnb, Wself, bself, Watt, batt);     // 0
    fill_kernel<<<(N_EDGES / 2 + 255) / 256, 256>>>(eidx);                    // 1
    gemm_xw<<<(N_NODES + 127) / 128, 128>>>(x);                               // 2
    conv0_kernel<<<(N_NODES * 32 + 255) / 256, 256>>>(b0, W1);                // 3 (profiled)
    attn_kernel<<<(N_NODES * 32 + 255) / 256, 256>>>();                       // 4
    conv1_kernel<<<(N_NODES * 32 + 255) / 256, 256>>>(b1, out);               // 5
}

// round 16
// speedup vs baseline: 2.0283x; 1.0832x over previous
#include <cuda_runtime.h>

// PTDNet-GCN fused pipeline, round 15:
//  - conv0 epilogue rebuilt: W1/att_a/att_b folded into one g_wc[10][32]
//    matrix (built in zero_prep); single-branch float4-vectorized epilogue
//    (lanes 0-9) replaces three divergent 32-iteration scalar loops.
//  - Everything else as R14 (best known).

#define N_NODES 100000
#define N_EDGES 1600000
#define IN_DIM  512
#define H0      32
#define H1      8
#define ZETA    1.01f
#define NB_ZERO 98            // ceil(100000/1024)
#define DSHIFT  6             // 64 slots per node
#define DSTRIDE 64

// ---------------- scratch (static device memory) ----------------------------
__device__ float  g_xw[N_NODES * H0];     // dinv0[row] * (x @ W0)
__device__ float  g_hw[N_NODES * H1];     // h @ W1
__device__ float  g_hws[N_NODES * H1];    // dinv1[row] * hw
__device__ int    g_cnt[N_NODES];         // in-degree (built by fill)
__device__ int    g_src[N_NODES * DSTRIDE]; // bucketed source nodes
__device__ float  g_mw[N_NODES * DSTRIDE];  // masked edge weight (bucket order)
__device__ float  g_dinv0[N_NODES];
__device__ float  g_dinv1[N_NODES];
__device__ float  g_u[N_NODES];
__device__ float  g_v[N_NODES];
__device__ float  g_wc[10 * 32];          // rows: 0-7 = W1 cols, 8 = att_a, 9 = att_b
__device__ float  g_cst;
// W0 fragments: [32 k16-steps][4 n-tiles][32 lanes] -> (b0_hi, b1_hi, b0_lo, b1_lo)
__device__ uint4  g_wf[32 * 4 * 32];

// ---------------- helpers ---------------------------------------------------
__device__ __forceinline__ float wred(float x) {
    x += __shfl_xor_sync(0xffffffffu, x, 16);
    x += __shfl_xor_sync(0xffffffffu, x, 8);
    x += __shfl_xor_sync(0xffffffffu, x, 4);
    x += __shfl_xor_sync(0xffffffffu, x, 2);
    x += __shfl_xor_sync(0xffffffffu, x, 1);
    return x;
}

__device__ __forceinline__ unsigned packbf(float lo, float hi) {
    unsigned r;
    asm("cvt.rn.bf16x2.f32 %0, %1, %2;" : "=r"(r) : "f"(hi), "f"(lo));
    return r;
}
__device__ __forceinline__ float bflo(unsigned u) { return __uint_as_float(u << 16); }
__device__ __forceinline__ float bfhi(unsigned u) { return __uint_as_float(u & 0xffff0000u); }

__device__ __forceinline__ void bfsplit2(float e0, float e1,
                                         unsigned& h, unsigned& l) {
    h = packbf(e0, e1);
    l = packbf(e0 - bflo(h), e1 - bfhi(h));
}

__device__ __forceinline__ void mma_bf16(float* d, const unsigned* a,
                                         unsigned b0, unsigned b1) {
    asm("mma.sync.aligned.m16n8k16.row.col.f32.bf16.bf16.f32 "
        "{%0,%1,%2,%3}, {%4,%5,%6,%7}, {%8,%9}, {%0,%1,%2,%3};"
        : "+f"(d[0]), "+f"(d[1]), "+f"(d[2]), "+f"(d[3])
        : "r"(a[0]), "r"(a[1]), "r"(a[2]), "r"(a[3]), "r"(b0), "r"(b1));
}

// ---------------- 1) zero counters + prep (g_wc, g_cst) + W swizzle ----------
__global__ __launch_bounds__(1024) void zero_prep(
        const float* __restrict__ W0, const float* __restrict__ W1,
        const float* __restrict__ Wnb, const float* __restrict__ bnb,
        const float* __restrict__ Wself, const float* __restrict__ bself,
        const float* __restrict__ Watt, const float* __restrict__ batt) {
    int i = blockIdx.x * 1024 + threadIdx.x;
    if (i < N_NODES) g_cnt[i] = 0;
    if (blockIdx.x == 0) {
        int t = threadIdx.x;
        if (t < 320) {
            int c = t >> 5, j = t & 31;
            float v = 0.f;
            if (c < 8) {
                v = W1[j * 8 + c];
            } else if (c == 8) {
#pragma unroll
                for (int q = 0; q < 8; ++q) v += Wnb[j * 8 + q] * Watt[q];
            } else {
#pragma unroll
                for (int q = 0; q < 8; ++q) v += Wself[j * 8 + q] * Watt[8 + q];
            }
            g_wc[c * 32 + j] = v;
        } else if (t == 320) {
            float c = batt[0];
#pragma unroll
            for (int q = 0; q < 8; ++q)
                c += bnb[q] * Watt[q] + bself[q] * Watt[8 + q];
            g_cst = c;
        }
    } else if (blockIdx.x <= 4) {
        // W fragment swizzle: idx over 32*4*32 = 4096 entries
        int idx = (blockIdx.x - 1) * 1024 + threadIdx.x;
        int s = idx >> 7;            // k16-step 0..31
        int t = (idx >> 5) & 3;      // n-tile
        int lane = idx & 31;
        int tig = lane & 3, gid = lane >> 2;
        int col = 8 * t + gid;
        float w00 = W0[(16 * s + 2 * tig) * 32 + col];
        float w01 = W0[(16 * s + 2 * tig + 1) * 32 + col];
        float w10 = W0[(16 * s + 2 * tig + 8) * 32 + col];
        float w11 = W0[(16 * s + 2 * tig + 9) * 32 + col];
        unsigned b0h, b0l, b1h, b1l;
        bfsplit2(w00, w01, b0h, b0l);
        bfsplit2(w10, w11, b1h, b1l);
        g_wf[idx] = make_uint4(b0h, b1h, b0l, b1l);
    }
}

// ---------------- 2) bucket fill: count + place in one pass ------------------
__global__ void fill_kernel(const int* __restrict__ eidx) {
    int t = blockIdx.x * blockDim.x + threadIdx.x;
    if (t >= N_EDGES / 2) return;
    int2 r = *(const int2*)(eidx + t * 2);
    int2 c = *(const int2*)(eidx + N_EDGES + t * 2);
    int p0 = atomicAdd(&g_cnt[c.x], 1);
    int p1 = atomicAdd(&g_cnt[c.y], 1);
    g_src[(c.x << DSHIFT) + p0] = r.x;
    g_src[(c.y << DSHIFT) + p1] = r.y;
}

// ---------------- 3) xw = dinv0 * (x @ W0)  (3-stage cp.async + bf16 mma) ----
#define KCHUNK 16
#define KPAD   20
#define NCHUNK (IN_DIM / KCHUNK)   // 32
#define NSTAGE 3
__global__ __launch_bounds__(128, 6) void gemm_xw(const float* __restrict__ x) {
    __shared__ float xs[NSTAGE][128][KPAD];   // 30720 B
    int tid = threadIdx.x;
    int lane = tid & 31;
    int warp = tid >> 5;            // 0..3
    int row0 = blockIdx.x * 128;
    int gid = lane >> 2, tig = lane & 3;
    int wrow = warp * 32;

    float acc[2][4][4];
#pragma unroll
    for (int m = 0; m < 2; ++m)
#pragma unroll
        for (int t = 0; t < 4; ++t)
#pragma unroll
            for (int r = 0; r < 4; ++r) acc[m][t][r] = 0.f;

    auto issue = [&](int c) {
        int stg = c % NSTAGE;
        int k0 = c * KCHUNK;
#pragma unroll
        for (int it = 0; it < 4; ++it) {
            int idx = tid + it * 128;        // 0..511 float4 slots
            int rr = idx >> 2;               // 0..127
            int cc = (idx & 3) * 4;          // 0,4,8,12
            int grow = row0 + rr;
            if (grow >= N_NODES) grow = N_NODES - 1;   // clamp (stores guarded)
            const float* src = x + (size_t)grow * IN_DIM + k0 + cc;
            unsigned dst = (unsigned)__cvta_generic_to_shared(&xs[stg][rr][cc]);
            asm volatile("cp.async.ca.shared.global [%0], [%1], 16;"
                         :: "r"(dst), "l"(src));
        }
        asm volatile("cp.async.commit_group;");
    };

    issue(0); issue(1);

    for (int c = 0; c < NCHUNK; ++c) {
        asm volatile("cp.async.wait_group 1;");
        __syncthreads();
        if (c + 2 < NCHUNK) issue(c + 2);
        else asm volatile("cp.async.commit_group;");   // keep 2 pending groups

        int stg = c % NSTAGE;

        float2 p[2][4];
        p[0][0] = *(const float2*)&xs[stg][wrow + gid     ][2 * tig];
        p[0][1] = *(const float2*)&xs[stg][wrow + gid + 8 ][2 * tig];
        p[0][2] = *(const float2*)&xs[stg][wrow + gid     ][2 * tig + 8];
        p[0][3] = *(const float2*)&xs[stg][wrow + gid + 8 ][2 * tig + 8];
        p[1][0] = *(const float2*)&xs[stg][wrow + gid + 16][2 * tig];
        p[1][1] = *(const float2*)&xs[stg][wrow + gid + 24][2 * tig];
        p[1][2] = *(const float2*)&xs[stg][wrow + gid + 16][2 * tig + 8];
        p[1][3] = *(const float2*)&xs[stg][wrow + gid + 24][2 * tig + 8];

        unsigned ah[2][4], al[2][4];
#pragma unroll
        for (int m = 0; m < 2; ++m)
#pragma unroll
            for (int j = 0; j < 4; ++j)
                bfsplit2(p[m][j].x, p[m][j].y, ah[m][j], al[m][j]);

#pragma unroll
        for (int t = 0; t < 4; ++t) {
            uint4 w = __ldg(&g_wf[(c * 4 + t) * 32 + lane]);
#pragma unroll
            for (int m = 0; m < 2; ++m) {
                mma_bf16(acc[m][t], ah[m], w.x, w.y);   // ah*bh
                mma_bf16(acc[m][t], al[m], w.x, w.y);   // al*bh
                mma_bf16(acc[m][t], ah[m], w.z, w.w);   // ah*bl
            }
        }
    }

    // epilogue: dinv0 = rsqrt(indeg+1); write scaled rows + g_dinv0
#pragma unroll
    for (int m = 0; m < 2; ++m) {
        int rA = row0 + wrow + m * 16 + gid;
        int rB = rA + 8;
        if (rA < N_NODES) {
            float dA = rsqrtf((float)g_cnt[rA] + 1.f);
            if (tig == 0) g_dinv0[rA] = dA;
#pragma unroll
            for (int t = 0; t < 4; ++t) {
                int col = t * 8 + tig * 2;
                *(float2*)(g_xw + rA * 32 + col) =
                    make_float2(acc[m][t][0] * dA, acc[m][t][1] * dA);
            }
        }
        if (rB < N_NODES) {
            float dB = rsqrtf((float)g_cnt[rB] + 1.f);
            if (tig == 0) g_dinv0[rB] = dB;
#pragma unroll
            for (int t = 0; t < 4; ++t) {
                int col = t * 8 + tig * 2;
                *(float2*)(g_xw + rB * 32 + col) =
                    make_float2(acc[m][t][2] * dB, acc[m][t][3] * dB);
            }
        }
    }
}

// ---------------- 4) conv0 + fused (hw, u, v) --------------------------------
__global__ __launch_bounds__(256) void conv0_kernel(const float* __restrict__ b0) {
    __shared__ float hsm[8][32];
    int warp = (blockIdx.x * blockDim.x + threadIdx.x) >> 5;
    int lane = threadIdx.x & 31;
    int w = threadIdx.x >> 5;
    if (warp >= N_NODES) return;
    int node = warp;
    int s = node << DSHIFT;
    int e = s + g_cnt[node];
    int g = lane >> 3;
    int f4 = (lane & 7) * 4;

    float4 acc;
    if (g == 0) acc = *(const float4*)(g_xw + node * 32 + f4);  // self (pre-scaled)
    else        acc = make_float4(0.f, 0.f, 0.f, 0.f);

    for (int p0 = s; p0 < e; p0 += 8) {
        int pA = p0 + g;
        int pB = p0 + 4 + g;
        int rA = (pA < e) ? g_src[pA] : -1;
        int rB = (pB < e) ? g_src[pB] : -1;
        if (rA >= 0) {
            float4 xv = *(const float4*)(g_xw + rA * 32 + f4);
            acc.x += xv.x; acc.y += xv.y; acc.z += xv.z; acc.w += xv.w;
        }
        if (rB >= 0) {
            float4 xv = *(const float4*)(g_xw + rB * 32 + f4);
            acc.x += xv.x; acc.y += xv.y; acc.z += xv.z; acc.w += xv.w;
        }
    }
    acc.x += __shfl_xor_sync(0xffffffffu, acc.x, 8);
    acc.y += __shfl_xor_sync(0xffffffffu, acc.y, 8);
    acc.z += __shfl_xor_sync(0xffffffffu, acc.z, 8);
    acc.w += __shfl_xor_sync(0xffffffffu, acc.w, 8);
    acc.x += __shfl_xor_sync(0xffffffffu, acc.x, 16);
    acc.y += __shfl_xor_sync(0xffffffffu, acc.y, 16);
    acc.z += __shfl_xor_sync(0xffffffffu, acc.z, 16);
    acc.w += __shfl_xor_sync(0xffffffffu, acc.w, 16);

    float dc = g_dinv0[node];
    if (g == 0) {
        hsm[w][f4 + 0] = dc * acc.x + __ldg(b0 + f4 + 0);
        hsm[w][f4 + 1] = dc * acc.y + __ldg(b0 + f4 + 1);
        hsm[w][f4 + 2] = dc * acc.z + __ldg(b0 + f4 + 2);
        hsm[w][f4 + 3] = dc * acc.w + __ldg(b0 + f4 + 3);
    }
    __syncwarp();

    // single-branch vectorized epilogue: lanes 0-9 each compute one output
    if (lane < 10) {
        float q = 0.f;
        const float4* wrow = (const float4*)(g_wc + lane * 32);
        const float4* h4 = (const float4*)hsm[w];
#pragma unroll
        for (int j = 0; j < 8; ++j) {
            float4 wv = __ldg(&wrow[j]);
            float4 hv = h4[j];
            q += wv.x * hv.x + wv.y * hv.y + wv.z * hv.z + wv.w * hv.w;
        }
        if (lane < 8)       g_hw[node * 8 + lane] = q;
        else if (lane == 8) g_u[node] = q;
        else                g_v[node] = q;
    }
}

// ---------------- 5) attention weights + dinv1 + hws -------------------------
__global__ __launch_bounds__(256) void attn_kernel() {
    int warp = (blockIdx.x * blockDim.x + threadIdx.x) >> 5;
    int lane = threadIdx.x & 31;
    if (warp >= N_NODES) return;
    int node = warp;
    float vc = g_v[node] + g_cst;
    int s = node << DSHIFT;
    int e = s + g_cnt[node];
    float sum = 0.f;
    for (int p0 = s; p0 < e; p0 += 32) {
        int p = p0 + lane;
        float mw = 0.f;
        if (p < e) {
            int r = g_src[p];
            float wgt = fmaxf(g_u[r] + vc, 0.f);
            float m = fminf(ZETA / (1.f + __expf(-wgt)), 1.f);
            mw = m * wgt;
            g_mw[p] = mw;
        }
        sum += mw;
    }
    sum = wred(sum);
    float d1 = rsqrtf(sum + 1.0f);
    if (lane == 0) g_dinv1[node] = d1;
    if (lane < 8) g_hws[node * 8 + lane] = d1 * g_hw[node * 8 + lane];
}

// ---------------- 6) conv1 ---------------------------------------------------
__global__ __launch_bounds__(256) void conv1_kernel(const float* __restrict__ b1,
                                                    float* __restrict__ out) {
    int warp = (blockIdx.x * blockDim.x + threadIdx.x) >> 5;
    int lane = threadIdx.x & 31;
    if (warp >= N_NODES) return;
    int node = warp;
    int s = node << DSHIFT;
    int e = s + g_cnt[node];
    int g = lane >> 3;
    int f = lane & 7;

    float acc = (g == 0) ? g_hws[node * 8 + f] : 0.f;  // self term

    for (int p0 = s; p0 < e; p0 += 8) {
        int pA = p0 + g;
        int pB = p0 + 4 + g;
        int rA = (pA < e) ? g_src[pA] : -1;
        int rB = (pB < e) ? g_src[pB] : -1;
        float cA = (pA < e) ? g_mw[pA] : 0.f;
        float cB = (pB < e) ? g_mw[pB] : 0.f;
        if (rA >= 0) acc += cA * g_hws[rA * 8 + f];
        if (rB >= 0) acc += cB * g_hws[rB * 8 + f];
    }
    acc += __shfl_xor_sync(0xffffffffu, acc, 8);
    acc += __shfl_xor_sync(0xffffffffu, acc, 16);

    if (lane < 8)
        out[node * 8 + lane] = g_dinv1[node] * acc + __ldg(b1 + lane);
}

// ---------------- launch -----------------------------------------------------
extern "C" void kernel_launch(void* const* d_in, const int* in_sizes, int n_in,
                              void* d_out, int out_size) {
    const float* x     = (const float*)d_in[0];
    const int*   eidx  = (const int*)  d_in[1];
    const float* W0    = (const float*)d_in[2];
    const float* b0    = (const float*)d_in[3];
    const float* W1    = (const float*)d_in[4];
    const float* b1    = (const float*)d_in[5];
    const float* Wnb   = (const float*)d_in[6];
    const float* bnb   = (const float*)d_in[7];
    const float* Wself = (const float*)d_in[8];
    const float* bself = (const float*)d_in[9];
    const float* Watt  = (const float*)d_in[10];
    const float* batt  = (const float*)d_in[11];
    float* out = (float*)d_out;

    zero_prep<<<NB_ZERO, 1024>>>(W0, W1, Wnb, bnb, Wself, bself, Watt, batt); // 0
    fill_kernel<<<(N_EDGES / 2 + 255) / 256, 256>>>(eidx);                    // 1
    gemm_xw<<<(N_NODES + 127) / 128, 128>>>(x);                               // 2
    conv0_kernel<<<(N_NODES * 32 + 255) / 256, 256>>>(b0);                    // 3 (profiled)
    attn_kernel<<<(N_NODES * 32 + 255) / 256, 256>>>();                       // 4
    conv1_kernel<<<(N_NODES * 32 + 255) / 256, 256>>>(b1, out);               // 5
}